// round 1
// baseline (speedup 1.0000x reference)
#include <cuda_runtime.h>

#define P_ 4096
#define PN_ 32
#define PE_ 128
#define B_ 4
#define M_ 1024
#define ME_ 16384
#define IN_ 64
#define HP_ 256
#define HP4_ 64
#define RD_ 256
#define HM_ 512
#define OUT_ 16
#define RTOT_ (IN_+HP_+HP4_)   // 384
#define EPS_ 1e-5f
#define SLOPE_ 0.01f

// ---------------- scratch (no runtime allocation allowed) ----------------
__device__ float g_H  [(size_t)P_*PN_*HP_];    // conv1 pre-agg   [131072,256]
__device__ float g_H1 [(size_t)P_*PN_*HP_];    // conv1 activated [131072,256]
__device__ float g_H2 [(size_t)P_*PN_*HP4_];   // conv2 pre-agg   [131072,64]
__device__ float g_R  [(size_t)P_*RTOT_];      // readout concat  [4096,384]
__device__ float g_E  [(size_t)P_*RD_];        // patch embed     [4096,256]
__device__ float g_NF [(size_t)P_*RD_];        // node feats      [4096,256]
__device__ float g_HM [(size_t)B_*M_*HM_];     // mesh conv1 pre-agg
__device__ float g_AGG[(size_t)B_*M_*HM_];     // mesh agg buffer
__device__ float g_HMn[(size_t)B_*M_*HM_];     // mesh h1 activated
__device__ float g_HM2[(size_t)B_*M_*HM_];     // mesh conv2 pre-agg
__device__ float g_HM2n[(size_t)B_*M_*HM_];    // mesh h2 activated
__device__ float g_mouts[B_*M_], g_mins[B_*M_];
__device__ int   g_cnt_in[B_*M_], g_rowstart[B_*M_], g_cursor[B_*M_];
__device__ int   g_srcs[B_*ME_];
__device__ float g_wgt [B_*ME_];
__device__ float g_mean[B_*HM_], g_istd[B_*HM_];
__device__ float g_block[B_*2*HM_];

// ---------------- generic tiled fp32 GEMM: C[M,N] = A[M,K] @ B[K,N] -------
// Requires M%BM==0, N%BN==0, K%BK==0, K%4==0 (all shapes here satisfy this).
template<int BM,int BN,int BK,int TM,int TN>
__global__ void gemm_kernel(const float* __restrict__ A,
                            const float* __restrict__ B,
                            float* __restrict__ C,
                            int Mdim, int Ndim, int Kdim)
{
    constexpr int THREADS = (BM/TM)*(BN/TN);
    __shared__ float As[BK][BM];
    __shared__ float Bs[BK][BN];

    int nblk = Ndim / BN;
    int bx = blockIdx.x % nblk;
    int by = blockIdx.x / nblk;
    int tid = threadIdx.x;
    int tx = tid % (BN/TN);
    int ty = tid / (BN/TN);

    const float* Ab = A + (size_t)by * BM * Kdim;
    const float* Bb = B + (size_t)bx * BN;

    float acc[TM][TN];
    #pragma unroll
    for (int i=0;i<TM;i++)
        #pragma unroll
        for (int j=0;j<TN;j++) acc[i][j]=0.f;

    for (int k0=0;k0<Kdim;k0+=BK) {
        // A tile: BM x BK, stored k-major in smem
        #pragma unroll
        for (int i=tid;i<BM*BK/4;i+=THREADS) {
            int row = i / (BK/4);
            int kq  = i % (BK/4);
            float4 v = *(const float4*)(Ab + (size_t)row*Kdim + k0 + kq*4);
            As[kq*4+0][row]=v.x; As[kq*4+1][row]=v.y;
            As[kq*4+2][row]=v.z; As[kq*4+3][row]=v.w;
        }
        // B tile: BK x BN
        #pragma unroll
        for (int i=tid;i<BK*BN/4;i+=THREADS) {
            int kk = i / (BN/4);
            int cq = i % (BN/4);
            *(float4*)&Bs[kk][cq*4] =
                *(const float4*)(Bb + (size_t)(k0+kk)*Ndim + cq*4);
        }
        __syncthreads();
        #pragma unroll
        for (int kk=0;kk<BK;kk++) {
            float a[TM], b[TN];
            #pragma unroll
            for (int i=0;i<TM;i+=4) *(float4*)&a[i] = *(const float4*)&As[kk][ty*TM+i];
            #pragma unroll
            for (int j=0;j<TN;j+=4) *(float4*)&b[j] = *(const float4*)&Bs[kk][tx*TN+j];
            #pragma unroll
            for (int i=0;i<TM;i++)
                #pragma unroll
                for (int j=0;j<TN;j++) acc[i][j] += a[i]*b[j];
        }
        __syncthreads();
    }
    float* Cb = C + (size_t)(by*BM)*Ndim + (size_t)bx*BN;
    #pragma unroll
    for (int i=0;i<TM;i++)
        #pragma unroll
        for (int j=0;j<TN;j+=4)
            *(float4*)(Cb + (size_t)(ty*TM+i)*Ndim + tx*TN + j) = *(float4*)&acc[i][j];
}

// ---------------- patch phase glue ----------------------------------------
__global__ void r0_kernel(const float* __restrict__ feats)
{
    int p = blockIdx.x, j = threadIdx.x;            // 64 threads
    const float* f = feats + (size_t)p*PN_*IN_;
    float s = 0.f;
    #pragma unroll
    for (int k=0;k<PN_;k++) s += f[k*IN_+j];
    g_R[(size_t)p*RTOT_ + j] = s*(1.f/PN_);
}

// One CTA per patch: degrees + weighted aggregation + GraphNorm + lrelu +
// mean readout. Thread j owns channel column j exclusively -> no atomics in
// the aggregation.
template<int C, bool WRITE_H>
__global__ void patch_agg_kernel(const float* __restrict__ H,
                                 const int* __restrict__ src,
                                 const int* __restrict__ dst,
                                 const float* __restrict__ ew,
                                 const float* __restrict__ gamma,
                                 const float* __restrict__ beta,
                                 const float* __restrict__ alpha,
                                 float* __restrict__ Hout,
                                 int r_off)
{
    int p = blockIdx.x;
    int j = threadIdx.x;                            // C threads
    __shared__ float Ag[PN_][C];
    __shared__ float outs[PN_], ins[PN_];
    __shared__ int   es[PE_], ed[PE_];
    __shared__ float ewt[PE_];
    __shared__ int   cnto[PN_], cnti[PN_];

    if (j < PN_) { cnto[j]=0; cnti[j]=0; }
    __syncthreads();

    const int*   sp = src + p*PE_;
    const int*   dp = dst + p*PE_;
    const float* wp = ew  + p*PE_;
    for (int e=j;e<PE_;e+=C) {
        int s = sp[e], d = dp[e];
        es[e]=s; ed[e]=d; ewt[e]=wp[e];
        atomicAdd(&cnto[s],1);
        atomicAdd(&cnti[d],1);
    }
    __syncthreads();
    if (j < PN_) {
        outs[j] = rsqrtf(fmaxf((float)cnto[j],1.f));
        ins[j]  = rsqrtf(fmaxf((float)cnti[j],1.f));
    }
    #pragma unroll
    for (int k=0;k<PN_;k++) Ag[k][j]=0.f;
    __syncthreads();

    const float* Hp = H + (size_t)p*PN_*C;
    for (int e=0;e<PE_;e++) {
        int s = es[e];
        Ag[ed[e]][j] += Hp[s*C + j] * outs[s] * ewt[e];
    }

    // GraphNorm over the 32 nodes of this column
    float xv[PN_];
    float s1 = 0.f;
    #pragma unroll
    for (int k=0;k<PN_;k++){ float v = Ag[k][j]*ins[k]; xv[k]=v; s1+=v; }
    float mean = s1*(1.f/PN_);
    float am   = alpha[j]*mean;
    float s2 = 0.f;
    #pragma unroll
    for (int k=0;k<PN_;k++){ float sb = xv[k]-am; s2 += sb*sb; }
    float istd = rsqrtf(s2*(1.f/PN_) + EPS_);
    float g = gamma[j], bb = beta[j];

    float rs = 0.f;
    float* Ho = WRITE_H ? (Hout + (size_t)p*PN_*C) : nullptr;
    #pragma unroll
    for (int k=0;k<PN_;k++) {
        float h = g*(xv[k]-am)*istd + bb;
        h = h>=0.f ? h : SLOPE_*h;
        if (WRITE_H) Ho[k*C + j] = h;
        rs += h;
    }
    g_R[(size_t)p*RTOT_ + r_off + j] = rs*(1.f/PN_);
}

// Row-wise InstanceNorm over 256 channels + lrelu
__global__ void inorm_kernel(const float* __restrict__ E, float* __restrict__ NF)
{
    int p = blockIdx.x, j = threadIdx.x;            // 256 threads
    __shared__ float sm[16];
    float v = E[(size_t)p*RD_ + j];

    float s1 = v;
    #pragma unroll
    for (int o=16;o>0;o>>=1) s1 += __shfl_xor_sync(0xffffffffu, s1, o);
    if ((j&31)==0) sm[j>>5] = s1;
    __syncthreads();
    if (j < 32) {
        float x = (j<8)? sm[j] : 0.f;
        #pragma unroll
        for (int o=4;o>0;o>>=1) x += __shfl_xor_sync(0xffffffffu, x, o);
        if (j==0) sm[8] = x;
    }
    __syncthreads();
    float mu = sm[8]*(1.f/RD_);
    float d  = v - mu;

    float s2 = d*d;
    #pragma unroll
    for (int o=16;o>0;o>>=1) s2 += __shfl_xor_sync(0xffffffffu, s2, o);
    if ((j&31)==0) sm[j>>5] = s2;
    __syncthreads();
    if (j < 32) {
        float x = (j<8)? sm[j] : 0.f;
        #pragma unroll
        for (int o=4;o>0;o>>=1) x += __shfl_xor_sync(0xffffffffu, x, o);
        if (j==0) sm[9] = x;
    }
    __syncthreads();
    float var = sm[9]*(1.f/RD_);
    float y = d * rsqrtf(var + EPS_);
    NF[(size_t)p*RD_ + j] = y>=0.f ? y : SLOPE_*y;
}

// ---------------- mesh phase glue -----------------------------------------
__global__ void mdeg_kernel(const int* __restrict__ msrc,
                            const int* __restrict__ mdst)
{
    int b = blockIdx.x, t = threadIdx.x;            // 1024 threads
    __shared__ int co[M_], ci[M_];
    co[t]=0; ci[t]=0;
    __syncthreads();
    const int* sp = msrc + b*ME_;
    const int* dp = mdst + b*ME_;
    for (int e=t;e<ME_;e+=M_) {
        atomicAdd(&co[sp[e]],1);
        atomicAdd(&ci[dp[e]],1);
    }
    __syncthreads();
    g_mouts[b*M_+t] = rsqrtf(fmaxf((float)co[t],1.f));
    g_mins [b*M_+t] = rsqrtf(fmaxf((float)ci[t],1.f));
    g_cnt_in[b*M_+t] = ci[t];
}

__global__ void mscan_kernel()
{
    int b = blockIdx.x, t = threadIdx.x;            // 1024 threads
    __shared__ int s[M_];
    int orig = g_cnt_in[b*M_+t];
    s[t] = orig;
    __syncthreads();
    for (int o=1;o<M_;o<<=1) {
        int u = (t>=o)? s[t-o] : 0;
        __syncthreads();
        s[t] += u;
        __syncthreads();
    }
    int st = s[t] - orig;                            // exclusive prefix
    g_rowstart[b*M_+t] = st;
    g_cursor  [b*M_+t] = st;
}

__global__ void mbucket_kernel(const int* __restrict__ msrc,
                               const int* __restrict__ mdst,
                               const float* __restrict__ mew)
{
    int eg = blockIdx.x*256 + threadIdx.x;
    if (eg >= B_*ME_) return;
    int b = eg >> 14;                                // ME = 2^14
    int s = msrc[eg], d = mdst[eg];
    int pos = atomicAdd(&g_cursor[b*M_+d], 1);
    g_srcs[b*ME_+pos] = s;
    g_wgt [b*ME_+pos] = mew[eg] * g_mouts[b*M_+s];
}

// Gather aggregation: one CTA per (node, 128-channel group).
__global__ void magg_kernel(const float* __restrict__ H, float* __restrict__ AGG)
{
    int node = blockIdx.x;                           // 0..4095
    int b = node >> 10;
    int n = node & (M_-1);
    int c = blockIdx.y*128 + threadIdx.x;
    int beg = g_rowstart[node];
    int end = (n==M_-1) ? ME_ : g_rowstart[node+1];
    const int*   sarr = g_srcs + b*ME_;
    const float* warr = g_wgt  + b*ME_;
    float acc = 0.f;
    for (int i=beg;i<end;i++)
        acc += H[(size_t)(b*M_ + sarr[i])*HM_ + c] * warr[i];
    AGG[(size_t)node*HM_ + c] = acc;
}

__global__ void mstats_kernel(const float* __restrict__ alpha)
{
    int b = blockIdx.x >> 2;
    int c = (blockIdx.x & 3)*128 + threadIdx.x;
    const float* A  = g_AGG  + (size_t)b*M_*HM_;
    const float* is = g_mins + b*M_;
    float s1 = 0.f;
    #pragma unroll 4
    for (int r=0;r<M_;r++) s1 += A[(size_t)r*HM_+c]*is[r];
    float mu = s1*(1.f/M_);
    float am = alpha[c]*mu;
    float s2 = 0.f;
    #pragma unroll 4
    for (int r=0;r<M_;r++) {
        float v = A[(size_t)r*HM_+c]*is[r] - am;
        s2 += v*v;
    }
    g_mean[b*HM_+c] = mu;
    g_istd[b*HM_+c] = rsqrtf(s2*(1.f/M_) + EPS_);
}

__global__ void mnorm_kernel(const float* __restrict__ gamma,
                             const float* __restrict__ beta,
                             const float* __restrict__ alpha,
                             float* __restrict__ Hn)
{
    size_t i = (size_t)blockIdx.x*256 + threadIdx.x; // over 4096*512
    int c   = (int)(i & (HM_-1));
    int row = (int)(i >> 9);
    int b   = row >> 10;
    float v  = g_AGG[i]*g_mins[row];
    float sb = v - alpha[c]*g_mean[b*HM_+c];
    float h  = gamma[c]*sb*g_istd[b*HM_+c] + beta[c];
    Hn[i] = h>=0.f ? h : SLOPE_*h;
}

__global__ void rmean_kernel(const float* __restrict__ Hn, int off)
{
    int b = blockIdx.x >> 2;
    int c = (blockIdx.x & 3)*128 + threadIdx.x;
    float s = 0.f;
    #pragma unroll 4
    for (int r=0;r<M_;r++) s += Hn[(size_t)(b*M_+r)*HM_ + c];
    g_block[b*2*HM_ + off + c] = s*(1.f/M_);
}

__global__ void final_kernel(const float* __restrict__ Wc, float* __restrict__ out)
{
    int t = threadIdx.x;                             // 256 threads
    float acc[OUT_];
    #pragma unroll
    for (int o=0;o<OUT_;o++) acc[o]=0.f;
    for (int i=t;i<B_*2*HM_;i+=256) {
        float v = g_block[i];
        v = v>=0.f ? v : SLOPE_*v;
        #pragma unroll
        for (int o=0;o<OUT_;o++) acc[o] += v*Wc[(size_t)i*OUT_+o];
    }
    __shared__ float red[OUT_][256];
    #pragma unroll
    for (int o=0;o<OUT_;o++) red[o][t]=acc[o];
    __syncthreads();
    for (int s=128;s>0;s>>=1) {
        if (t<s) {
            #pragma unroll
            for (int o=0;o<OUT_;o++) red[o][t]+=red[o][t+s];
        }
        __syncthreads();
    }
    if (t<OUT_) out[t]=red[t][0];
}

// ---------------- launcher -------------------------------------------------
extern "C" void kernel_launch(void* const* d_in, const int* in_sizes, int n_in,
                              void* d_out, int out_size)
{
    (void)in_sizes; (void)n_in; (void)out_size;
    const float* feats = (const float*)d_in[0];
    const int*   psrc  = (const int*)  d_in[1];
    const int*   pdst  = (const int*)  d_in[2];
    const float* pew   = (const float*)d_in[3];
    const int*   msrc  = (const int*)  d_in[4];
    const int*   mdst  = (const int*)  d_in[5];
    const float* mew   = (const float*)d_in[6];
    const float* Wp1   = (const float*)d_in[7];
    const float* Wp2   = (const float*)d_in[8];
    const float* W_emb = (const float*)d_in[9];
    const float* gp1_g = (const float*)d_in[10];
    const float* gp1_b = (const float*)d_in[11];
    const float* gp1_a = (const float*)d_in[12];
    const float* gp2_g = (const float*)d_in[13];
    const float* gp2_b = (const float*)d_in[14];
    const float* gp2_a = (const float*)d_in[15];
    const float* gm1_g = (const float*)d_in[16];
    const float* gm1_b = (const float*)d_in[17];
    const float* gm1_a = (const float*)d_in[18];
    const float* gm2_g = (const float*)d_in[19];
    const float* gm2_b = (const float*)d_in[20];
    const float* gm2_a = (const float*)d_in[21];
    const float* Wm1   = (const float*)d_in[22];
    const float* Wm2   = (const float*)d_in[23];
    const float* Wc    = (const float*)d_in[24];
    float* out = (float*)d_out;

    float *pH,*pH1,*pH2,*pR,*pE,*pNF,*pHM,*pAGG,*pHMn,*pHM2,*pHM2n;
    cudaGetSymbolAddress((void**)&pH,   g_H);
    cudaGetSymbolAddress((void**)&pH1,  g_H1);
    cudaGetSymbolAddress((void**)&pH2,  g_H2);
    cudaGetSymbolAddress((void**)&pR,   g_R);
    cudaGetSymbolAddress((void**)&pE,   g_E);
    cudaGetSymbolAddress((void**)&pNF,  g_NF);
    cudaGetSymbolAddress((void**)&pHM,  g_HM);
    cudaGetSymbolAddress((void**)&pAGG, g_AGG);
    cudaGetSymbolAddress((void**)&pHMn, g_HMn);
    cudaGetSymbolAddress((void**)&pHM2, g_HM2);
    cudaGetSymbolAddress((void**)&pHM2n,g_HM2n);

    // ---- patch phase ----
    r0_kernel<<<P_, IN_>>>(feats);
    gemm_kernel<128,128,16,8,8><<<(P_*PN_/128)*(HP_/128), 256>>>(
        feats, Wp1, pH, P_*PN_, HP_, IN_);
    patch_agg_kernel<HP_,true><<<P_, HP_>>>(
        pH, psrc, pdst, pew, gp1_g, gp1_b, gp1_a, pH1, IN_);
    gemm_kernel<128,64,16,8,4><<<(P_*PN_/128)*(HP4_/64), 256>>>(
        pH1, Wp2, pH2, P_*PN_, HP4_, HP_);
    patch_agg_kernel<HP4_,false><<<P_, HP4_>>>(
        pH2, psrc, pdst, pew, gp2_g, gp2_b, gp2_a, nullptr, IN_+HP_);
    gemm_kernel<128,128,16,8,8><<<(P_/128)*(RD_/128), 256>>>(
        pR, W_emb, pE, P_, RD_, RTOT_);
    inorm_kernel<<<P_, RD_>>>(pE, pNF);

    // ---- mesh CSR build (shared by both layers) ----
    mdeg_kernel<<<B_, M_>>>(msrc, mdst);
    mscan_kernel<<<B_, M_>>>();
    mbucket_kernel<<<B_*ME_/256, 256>>>(msrc, mdst, mew);

    // ---- mesh layer 1 ----
    gemm_kernel<128,128,16,8,8><<<(B_*M_/128)*(HM_/128), 256>>>(
        pNF, Wm1, pHM, B_*M_, HM_, RD_);
    magg_kernel<<<dim3(B_*M_, HM_/128), 128>>>(pHM, pAGG);
    mstats_kernel<<<B_*4, 128>>>(gm1_a);
    mnorm_kernel<<<B_*M_*HM_/256, 256>>>(gm1_g, gm1_b, gm1_a, pHMn);
    rmean_kernel<<<B_*4, 128>>>(pHMn, 0);

    // ---- mesh layer 2 ----
    gemm_kernel<128,128,16,8,8><<<(B_*M_/128)*(HM_/128), 256>>>(
        pHMn, Wm2, pHM2, B_*M_, HM_, HM_);
    magg_kernel<<<dim3(B_*M_, HM_/128), 128>>>(pHM2, pAGG);
    mstats_kernel<<<B_*4, 128>>>(gm2_a);
    mnorm_kernel<<<B_*M_*HM_/256, 256>>>(gm2_g, gm2_b, gm2_a, pHM2n);
    rmean_kernel<<<B_*4, 128>>>(pHM2n, HM_);

    // ---- classifier ----
    final_kernel<<<1, 256>>>(Wc, out);
}

// round 2
// speedup vs baseline: 1.2934x; 1.2934x over previous
#include <cuda_runtime.h>
#include <cstdint>

#define P_ 4096
#define PN_ 32
#define PE_ 128
#define B_ 4
#define M_ 1024
#define ME_ 16384
#define IN_ 64
#define HP_ 256
#define HP4_ 64
#define RD_ 256
#define HM_ 512
#define OUT_ 16
#define RTOT_ (IN_+HP_+HP4_)   // 384
#define EPS_ 1e-5f
#define SLOPE_ 0.01f

// ---------------- scratch (no runtime allocation allowed) ----------------
__device__ float g_H  [(size_t)P_*PN_*HP_];    // conv1 pre-agg   [131072,256]
__device__ float g_H1 [(size_t)P_*PN_*HP_];    // conv1 activated [131072,256]
__device__ float g_H2 [(size_t)P_*PN_*HP4_];   // conv2 pre-agg   [131072,64]
__device__ float g_R  [(size_t)P_*RTOT_];      // readout concat  [4096,384]
__device__ float g_E  [(size_t)P_*RD_];        // patch embed     [4096,256]
__device__ float g_NF [(size_t)P_*RD_];        // node feats      [4096,256]
__device__ float g_HM [(size_t)B_*M_*HM_];     // mesh conv1 pre-agg
__device__ float g_AGG[(size_t)B_*M_*HM_];     // mesh agg buffer
__device__ float g_HMn[(size_t)B_*M_*HM_];     // mesh h1 activated
__device__ float g_HM2[(size_t)B_*M_*HM_];     // mesh conv2 pre-agg
__device__ float g_HM2n[(size_t)B_*M_*HM_];    // mesh h2 activated
__device__ float g_mouts[B_*M_], g_mins[B_*M_];
__device__ int   g_cnt_in[B_*M_], g_rowstart[B_*M_], g_cursor[B_*M_];
__device__ int   g_srcs[B_*ME_];
__device__ float g_wgt [B_*ME_];
__device__ float g_mean[B_*HM_], g_istd[B_*HM_];
__device__ float g_block[B_*2*HM_];

// ---------------- tf32 tensor-core GEMM ----------------------------------
__device__ __forceinline__ uint32_t f2tf32(float f) {
    uint32_t u;
    asm("cvt.rna.tf32.f32 %0, %1;" : "=r"(u) : "f"(f));
    return u;
}
__device__ __forceinline__ uint32_t smem_u32(const void* p) {
    return static_cast<uint32_t>(__cvta_generic_to_shared(p));
}
__device__ __forceinline__ void ldsm_x4(uint32_t& r0, uint32_t& r1,
                                        uint32_t& r2, uint32_t& r3, uint32_t addr) {
    asm volatile("ldmatrix.sync.aligned.m8n8.x4.shared.b16 {%0,%1,%2,%3}, [%4];\n"
                 : "=r"(r0), "=r"(r1), "=r"(r2), "=r"(r3) : "r"(addr));
}
__device__ __forceinline__ void mma_tf32(float* c, const uint32_t* a,
                                         uint32_t b0, uint32_t b1) {
    asm volatile(
        "mma.sync.aligned.m16n8k8.row.col.f32.tf32.tf32.f32 "
        "{%0,%1,%2,%3}, {%4,%5,%6,%7}, {%8,%9}, {%0,%1,%2,%3};\n"
        : "+f"(c[0]), "+f"(c[1]), "+f"(c[2]), "+f"(c[3])
        : "r"(a[0]), "r"(a[1]), "r"(a[2]), "r"(a[3]), "r"(b0), "r"(b1));
}

// C[M,N] = A[M,K] @ B[K,N]; fp32 in/out, tf32 tensor compute, fp32 accum.
// Requires M%BM==0, N%BN==0, K%32==0.
template<int BM, int BN>
__global__ void __launch_bounds__(256)
gemm_tf32(const float* __restrict__ A, const float* __restrict__ B,
          float* __restrict__ C, int Mdim, int Ndim, int Kdim)
{
    constexpr int BK  = 32;
    constexpr int WM  = 32;           // warps 4 (M) x 2 (N)
    constexpr int WN  = BN / 2;       // 64 or 32
    constexpr int MT  = WM / 16;      // 2
    constexpr int NT  = WN / 8;       // 8 or 4
    constexpr int ASR = BK + 4;       // 36: LDSM-conflict-free row stride
    constexpr int BSR = BN + 8;       // 136/72: 8 mod 32 -> conflict-free LDS
    constexpr int ASZ = BM * ASR;
    constexpr int BSZ = BK * BSR;
    constexpr int ALD = BM * BK / 4 / 256;   // float4/thread for A stage (4)
    constexpr int BLD = BK * BN / 4 / 256;   // 4 (BN=128) or 2 (BN=64)

    extern __shared__ uint32_t sm_[];
    uint32_t* As = sm_;               // [2][BM][ASR], m-major
    uint32_t* Bs = sm_ + 2 * ASZ;     // [2][BK][BSR], k-major

    const int tid  = threadIdx.x;
    const int lane = tid & 31;
    const int wid  = tid >> 5;
    const int nblk = Ndim / BN;
    const int bx = blockIdx.x % nblk;
    const int by = blockIdx.x / nblk;
    const float* Ab = A + (size_t)by * BM * Kdim;
    const float* Bb = B + (size_t)bx * BN;

    const int wm = (wid >> 1) * WM;
    const int wn = (wid & 1) * WN;

    float c[MT][NT][4];
    #pragma unroll
    for (int i = 0; i < MT; i++)
        #pragma unroll
        for (int j = 0; j < NT; j++)
            #pragma unroll
            for (int q = 0; q < 4; q++) c[i][j][q] = 0.f;

    float4 pa[ALD], pb[BLD];

    auto ldgA = [&](int k0) {
        #pragma unroll
        for (int i = 0; i < ALD; i++) {
            int lin = tid + i * 256;
            int row = lin >> 3;               // /(BK/4)
            int kq  = lin & 7;
            pa[i] = *(const float4*)(Ab + (size_t)row * Kdim + k0 + kq * 4);
        }
    };
    auto ldgB = [&](int k0) {
        #pragma unroll
        for (int i = 0; i < BLD; i++) {
            int lin = tid + i * 256;
            int kr = lin / (BN / 4);
            int nq = lin % (BN / 4);
            pb[i] = *(const float4*)(Bb + (size_t)(k0 + kr) * Ndim + nq * 4);
        }
    };
    auto stsA = [&](int buf) {
        uint32_t* base = As + buf * ASZ;
        #pragma unroll
        for (int i = 0; i < ALD; i++) {
            int lin = tid + i * 256;
            int row = lin >> 3;
            int kq  = lin & 7;
            uint4 v = make_uint4(f2tf32(pa[i].x), f2tf32(pa[i].y),
                                 f2tf32(pa[i].z), f2tf32(pa[i].w));
            *(uint4*)(base + row * ASR + kq * 4) = v;
        }
    };
    auto stsB = [&](int buf) {
        uint32_t* base = Bs + buf * BSZ;
        #pragma unroll
        for (int i = 0; i < BLD; i++) {
            int lin = tid + i * 256;
            int kr = lin / (BN / 4);
            int nq = lin % (BN / 4);
            uint4 v = make_uint4(f2tf32(pb[i].x), f2tf32(pb[i].y),
                                 f2tf32(pb[i].z), f2tf32(pb[i].w));
            *(uint4*)(base + kr * BSR + nq * 4) = v;
        }
    };

    const int arow = wm + (lane & 15);
    const int acol = (lane >> 4) * 4;
    const int bn0  = wn + (lane >> 2);
    const int bk0  = lane & 3;

    auto compute = [&](int buf) {
        uint32_t* Abs = As + buf * ASZ;
        uint32_t* Bbs = Bs + buf * BSZ;
        #pragma unroll
        for (int ks = 0; ks < 4; ks++) {
            uint32_t a[MT][4];
            #pragma unroll
            for (int i = 0; i < MT; i++) {
                uint32_t addr = smem_u32(Abs + (arow + i * 16) * ASR + ks * 8 + acol);
                ldsm_x4(a[i][0], a[i][1], a[i][2], a[i][3], addr);
            }
            uint32_t b0[NT], b1[NT];
            #pragma unroll
            for (int j = 0; j < NT; j++) {
                b0[j] = Bbs[(ks * 8 + bk0) * BSR + bn0 + j * 8];
                b1[j] = Bbs[(ks * 8 + 4 + bk0) * BSR + bn0 + j * 8];
            }
            #pragma unroll
            for (int i = 0; i < MT; i++)
                #pragma unroll
                for (int j = 0; j < NT; j++)
                    mma_tf32(c[i][j], a[i], b0[j], b1[j]);
        }
    };

    const int NKT = Kdim / BK;
    ldgA(0); ldgB(0);
    stsA(0); stsB(0);
    __syncthreads();
    for (int kt = 0; kt < NKT; kt++) {
        if (kt + 1 < NKT) { ldgA((kt + 1) * BK); ldgB((kt + 1) * BK); }
        compute(kt & 1);
        if (kt + 1 < NKT) { stsA((kt + 1) & 1); stsB((kt + 1) & 1); }
        __syncthreads();
    }

    float* Cb = C + (size_t)(by * BM + wm) * Ndim + bx * BN + wn;
    const int r0 = lane >> 2;
    const int c0 = (lane & 3) * 2;
    #pragma unroll
    for (int i = 0; i < MT; i++)
        #pragma unroll
        for (int j = 0; j < NT; j++) {
            *(float2*)(Cb + (size_t)(i * 16 + r0) * Ndim + j * 8 + c0) =
                make_float2(c[i][j][0], c[i][j][1]);
            *(float2*)(Cb + (size_t)(i * 16 + r0 + 8) * Ndim + j * 8 + c0) =
                make_float2(c[i][j][2], c[i][j][3]);
        }
}

// ---------------- patch phase glue ----------------------------------------
__global__ void r0_kernel(const float* __restrict__ feats)
{
    int p = blockIdx.x, j = threadIdx.x;            // 64 threads
    const float* f = feats + (size_t)p*PN_*IN_;
    float s = 0.f;
    #pragma unroll
    for (int k=0;k<PN_;k++) s += f[k*IN_+j];
    g_R[(size_t)p*RTOT_ + j] = s*(1.f/PN_);
}

template<int C, bool WRITE_H>
__global__ void patch_agg_kernel(const float* __restrict__ H,
                                 const int* __restrict__ src,
                                 const int* __restrict__ dst,
                                 const float* __restrict__ ew,
                                 const float* __restrict__ gamma,
                                 const float* __restrict__ beta,
                                 const float* __restrict__ alpha,
                                 float* __restrict__ Hout,
                                 int r_off)
{
    int p = blockIdx.x;
    int j = threadIdx.x;                            // C threads
    __shared__ float Ag[PN_][C];
    __shared__ float outs[PN_], ins[PN_];
    __shared__ int   es[PE_], ed[PE_];
    __shared__ float ewt[PE_];
    __shared__ int   cnto[PN_], cnti[PN_];

    if (j < PN_) { cnto[j]=0; cnti[j]=0; }
    __syncthreads();

    const int*   sp = src + p*PE_;
    const int*   dp = dst + p*PE_;
    const float* wp = ew  + p*PE_;
    for (int e=j;e<PE_;e+=C) {
        int s = sp[e], d = dp[e];
        es[e]=s; ed[e]=d; ewt[e]=wp[e];
        atomicAdd(&cnto[s],1);
        atomicAdd(&cnti[d],1);
    }
    __syncthreads();
    if (j < PN_) {
        outs[j] = rsqrtf(fmaxf((float)cnto[j],1.f));
        ins[j]  = rsqrtf(fmaxf((float)cnti[j],1.f));
    }
    #pragma unroll
    for (int k=0;k<PN_;k++) Ag[k][j]=0.f;
    __syncthreads();

    const float* Hp = H + (size_t)p*PN_*C;
    for (int e=0;e<PE_;e++) {
        int s = es[e];
        Ag[ed[e]][j] += Hp[s*C + j] * outs[s] * ewt[e];
    }

    float xv[PN_];
    float s1 = 0.f;
    #pragma unroll
    for (int k=0;k<PN_;k++){ float v = Ag[k][j]*ins[k]; xv[k]=v; s1+=v; }
    float mean = s1*(1.f/PN_);
    float am   = alpha[j]*mean;
    float s2 = 0.f;
    #pragma unroll
    for (int k=0;k<PN_;k++){ float sb = xv[k]-am; s2 += sb*sb; }
    float istd = rsqrtf(s2*(1.f/PN_) + EPS_);
    float g = gamma[j], bb = beta[j];

    float rs = 0.f;
    float* Ho = WRITE_H ? (Hout + (size_t)p*PN_*C) : nullptr;
    #pragma unroll
    for (int k=0;k<PN_;k++) {
        float h = g*(xv[k]-am)*istd + bb;
        h = h>=0.f ? h : SLOPE_*h;
        if (WRITE_H) Ho[k*C + j] = h;
        rs += h;
    }
    g_R[(size_t)p*RTOT_ + r_off + j] = rs*(1.f/PN_);
}

__global__ void inorm_kernel(const float* __restrict__ E, float* __restrict__ NF)
{
    int p = blockIdx.x, j = threadIdx.x;            // 256 threads
    __shared__ float sm[16];
    float v = E[(size_t)p*RD_ + j];

    float s1 = v;
    #pragma unroll
    for (int o=16;o>0;o>>=1) s1 += __shfl_xor_sync(0xffffffffu, s1, o);
    if ((j&31)==0) sm[j>>5] = s1;
    __syncthreads();
    if (j < 32) {
        float x = (j<8)? sm[j] : 0.f;
        #pragma unroll
        for (int o=4;o>0;o>>=1) x += __shfl_xor_sync(0xffffffffu, x, o);
        if (j==0) sm[8] = x;
    }
    __syncthreads();
    float mu = sm[8]*(1.f/RD_);
    float d  = v - mu;

    float s2 = d*d;
    #pragma unroll
    for (int o=16;o>0;o>>=1) s2 += __shfl_xor_sync(0xffffffffu, s2, o);
    if ((j&31)==0) sm[j>>5] = s2;
    __syncthreads();
    if (j < 32) {
        float x = (j<8)? sm[j] : 0.f;
        #pragma unroll
        for (int o=4;o>0;o>>=1) x += __shfl_xor_sync(0xffffffffu, x, o);
        if (j==0) sm[9] = x;
    }
    __syncthreads();
    float var = sm[9]*(1.f/RD_);
    float y = d * rsqrtf(var + EPS_);
    NF[(size_t)p*RD_ + j] = y>=0.f ? y : SLOPE_*y;
}

// ---------------- mesh phase glue -----------------------------------------
__global__ void mdeg_kernel(const int* __restrict__ msrc,
                            const int* __restrict__ mdst)
{
    int b = blockIdx.x, t = threadIdx.x;            // 1024 threads
    __shared__ int co[M_], ci[M_];
    co[t]=0; ci[t]=0;
    __syncthreads();
    const int* sp = msrc + b*ME_;
    const int* dp = mdst + b*ME_;
    for (int e=t;e<ME_;e+=M_) {
        atomicAdd(&co[sp[e]],1);
        atomicAdd(&ci[dp[e]],1);
    }
    __syncthreads();
    g_mouts[b*M_+t] = rsqrtf(fmaxf((float)co[t],1.f));
    g_mins [b*M_+t] = rsqrtf(fmaxf((float)ci[t],1.f));
    g_cnt_in[b*M_+t] = ci[t];
}

__global__ void mscan_kernel()
{
    int b = blockIdx.x, t = threadIdx.x;            // 1024 threads
    __shared__ int s[M_];
    int orig = g_cnt_in[b*M_+t];
    s[t] = orig;
    __syncthreads();
    for (int o=1;o<M_;o<<=1) {
        int u = (t>=o)? s[t-o] : 0;
        __syncthreads();
        s[t] += u;
        __syncthreads();
    }
    int st = s[t] - orig;                            // exclusive prefix
    g_rowstart[b*M_+t] = st;
    g_cursor  [b*M_+t] = st;
}

__global__ void mbucket_kernel(const int* __restrict__ msrc,
                               const int* __restrict__ mdst,
                               const float* __restrict__ mew)
{
    int eg = blockIdx.x*256 + threadIdx.x;
    if (eg >= B_*ME_) return;
    int b = eg >> 14;                                // ME = 2^14
    int s = msrc[eg], d = mdst[eg];
    int pos = atomicAdd(&g_cursor[b*M_+d], 1);
    g_srcs[b*ME_+pos] = s;
    g_wgt [b*ME_+pos] = mew[eg] * g_mouts[b*M_+s];
}

__global__ void magg_kernel(const float* __restrict__ H, float* __restrict__ AGG)
{
    int node = blockIdx.x;                           // 0..4095
    int b = node >> 10;
    int n = node & (M_-1);
    int c = blockIdx.y*128 + threadIdx.x;
    int beg = g_rowstart[node];
    int end = (n==M_-1) ? ME_ : g_rowstart[node+1];
    const int*   sarr = g_srcs + b*ME_;
    const float* warr = g_wgt  + b*ME_;
    float acc = 0.f;
    for (int i=beg;i<end;i++)
        acc += H[(size_t)(b*M_ + sarr[i])*HM_ + c] * warr[i];
    AGG[(size_t)node*HM_ + c] = acc;
}

__global__ void mstats_kernel(const float* __restrict__ alpha)
{
    int b = blockIdx.x >> 2;
    int c = (blockIdx.x & 3)*128 + threadIdx.x;
    const float* A  = g_AGG  + (size_t)b*M_*HM_;
    const float* is = g_mins + b*M_;
    float s1 = 0.f;
    #pragma unroll 4
    for (int r=0;r<M_;r++) s1 += A[(size_t)r*HM_+c]*is[r];
    float mu = s1*(1.f/M_);
    float am = alpha[c]*mu;
    float s2 = 0.f;
    #pragma unroll 4
    for (int r=0;r<M_;r++) {
        float v = A[(size_t)r*HM_+c]*is[r] - am;
        s2 += v*v;
    }
    g_mean[b*HM_+c] = mu;
    g_istd[b*HM_+c] = rsqrtf(s2*(1.f/M_) + EPS_);
}

__global__ void mnorm_kernel(const float* __restrict__ gamma,
                             const float* __restrict__ beta,
                             const float* __restrict__ alpha,
                             float* __restrict__ Hn)
{
    size_t i = (size_t)blockIdx.x*256 + threadIdx.x; // over 4096*512
    int c   = (int)(i & (HM_-1));
    int row = (int)(i >> 9);
    int b   = row >> 10;
    float v  = g_AGG[i]*g_mins[row];
    float sb = v - alpha[c]*g_mean[b*HM_+c];
    float h  = gamma[c]*sb*g_istd[b*HM_+c] + beta[c];
    Hn[i] = h>=0.f ? h : SLOPE_*h;
}

__global__ void rmean_kernel(const float* __restrict__ Hn, int off)
{
    int b = blockIdx.x >> 2;
    int c = (blockIdx.x & 3)*128 + threadIdx.x;
    float s = 0.f;
    #pragma unroll 4
    for (int r=0;r<M_;r++) s += Hn[(size_t)(b*M_+r)*HM_ + c];
    g_block[b*2*HM_ + off + c] = s*(1.f/M_);
}

__global__ void final_kernel(const float* __restrict__ Wc, float* __restrict__ out)
{
    int t = threadIdx.x;                             // 256 threads
    float acc[OUT_];
    #pragma unroll
    for (int o=0;o<OUT_;o++) acc[o]=0.f;
    for (int i=t;i<B_*2*HM_;i+=256) {
        float v = g_block[i];
        v = v>=0.f ? v : SLOPE_*v;
        #pragma unroll
        for (int o=0;o<OUT_;o++) acc[o] += v*Wc[(size_t)i*OUT_+o];
    }
    __shared__ float red[OUT_][256];
    #pragma unroll
    for (int o=0;o<OUT_;o++) red[o][t]=acc[o];
    __syncthreads();
    for (int s=128;s>0;s>>=1) {
        if (t<s) {
            #pragma unroll
            for (int o=0;o<OUT_;o++) red[o][t]+=red[o][t+s];
        }
        __syncthreads();
    }
    if (t<OUT_) out[t]=red[t][0];
}

// ---------------- launcher -------------------------------------------------
extern "C" void kernel_launch(void* const* d_in, const int* in_sizes, int n_in,
                              void* d_out, int out_size)
{
    (void)in_sizes; (void)n_in; (void)out_size;
    const float* feats = (const float*)d_in[0];
    const int*   psrc  = (const int*)  d_in[1];
    const int*   pdst  = (const int*)  d_in[2];
    const float* pew   = (const float*)d_in[3];
    const int*   msrc  = (const int*)  d_in[4];
    const int*   mdst  = (const int*)  d_in[5];
    const float* mew   = (const float*)d_in[6];
    const float* Wp1   = (const float*)d_in[7];
    const float* Wp2   = (const float*)d_in[8];
    const float* W_emb = (const float*)d_in[9];
    const float* gp1_g = (const float*)d_in[10];
    const float* gp1_b = (const float*)d_in[11];
    const float* gp1_a = (const float*)d_in[12];
    const float* gp2_g = (const float*)d_in[13];
    const float* gp2_b = (const float*)d_in[14];
    const float* gp2_a = (const float*)d_in[15];
    const float* gm1_g = (const float*)d_in[16];
    const float* gm1_b = (const float*)d_in[17];
    const float* gm1_a = (const float*)d_in[18];
    const float* gm2_g = (const float*)d_in[19];
    const float* gm2_b = (const float*)d_in[20];
    const float* gm2_a = (const float*)d_in[21];
    const float* Wm1   = (const float*)d_in[22];
    const float* Wm2   = (const float*)d_in[23];
    const float* Wc    = (const float*)d_in[24];
    float* out = (float*)d_out;

    float *pH,*pH1,*pH2,*pR,*pE,*pNF,*pHM,*pAGG,*pHMn,*pHM2,*pHM2n;
    cudaGetSymbolAddress((void**)&pH,   g_H);
    cudaGetSymbolAddress((void**)&pH1,  g_H1);
    cudaGetSymbolAddress((void**)&pH2,  g_H2);
    cudaGetSymbolAddress((void**)&pR,   g_R);
    cudaGetSymbolAddress((void**)&pE,   g_E);
    cudaGetSymbolAddress((void**)&pNF,  g_NF);
    cudaGetSymbolAddress((void**)&pHM,  g_HM);
    cudaGetSymbolAddress((void**)&pAGG, g_AGG);
    cudaGetSymbolAddress((void**)&pHMn, g_HMn);
    cudaGetSymbolAddress((void**)&pHM2, g_HM2);
    cudaGetSymbolAddress((void**)&pHM2n,g_HM2n);

    // dynamic smem sizes for the tf32 GEMM configs
    const int SM128 = (2*128*36 + 2*32*136) * 4;   // 71680 B
    const int SM64  = (2*128*36 + 2*32*72)  * 4;   // 55296 B
    cudaFuncSetAttribute(gemm_tf32<128,128>,
                         cudaFuncAttributeMaxDynamicSharedMemorySize, SM128);
    cudaFuncSetAttribute(gemm_tf32<128,64>,
                         cudaFuncAttributeMaxDynamicSharedMemorySize, SM64);

    // ---- patch phase ----
    r0_kernel<<<P_, IN_>>>(feats);
    gemm_tf32<128,128><<<(P_*PN_/128)*(HP_/128), 256, SM128>>>(
        feats, Wp1, pH, P_*PN_, HP_, IN_);
    patch_agg_kernel<HP_,true><<<P_, HP_>>>(
        pH, psrc, pdst, pew, gp1_g, gp1_b, gp1_a, pH1, IN_);
    gemm_tf32<128,64><<<(P_*PN_/128)*(HP4_/64), 256, SM64>>>(
        pH1, Wp2, pH2, P_*PN_, HP4_, HP_);
    patch_agg_kernel<HP4_,false><<<P_, HP4_>>>(
        pH2, psrc, pdst, pew, gp2_g, gp2_b, gp2_a, nullptr, IN_+HP_);
    gemm_tf32<128,128><<<(P_/128)*(RD_/128), 256, SM128>>>(
        pR, W_emb, pE, P_, RD_, RTOT_);
    inorm_kernel<<<P_, RD_>>>(pE, pNF);

    // ---- mesh CSR build (shared by both layers) ----
    mdeg_kernel<<<B_, M_>>>(msrc, mdst);
    mscan_kernel<<<B_, M_>>>();
    mbucket_kernel<<<B_*ME_/256, 256>>>(msrc, mdst, mew);

    // ---- mesh layer 1 ----
    gemm_tf32<128,128><<<(B_*M_/128)*(HM_/128), 256, SM128>>>(
        pNF, Wm1, pHM, B_*M_, HM_, RD_);
    magg_kernel<<<dim3(B_*M_, HM_/128), 128>>>(pHM, pAGG);
    mstats_kernel<<<B_*4, 128>>>(gm1_a);
    mnorm_kernel<<<B_*M_*HM_/256, 256>>>(gm1_g, gm1_b, gm1_a, pHMn);
    rmean_kernel<<<B_*4, 128>>>(pHMn, 0);

    // ---- mesh layer 2 ----
    gemm_tf32<128,128><<<(B_*M_/128)*(HM_/128), 256, SM128>>>(
        pHMn, Wm2, pHM2, B_*M_, HM_, HM_);
    magg_kernel<<<dim3(B_*M_, HM_/128), 128>>>(pHM2, pAGG);
    mstats_kernel<<<B_*4, 128>>>(gm2_a);
    mnorm_kernel<<<B_*M_*HM_/256, 256>>>(gm2_g, gm2_b, gm2_a, pHM2n);
    rmean_kernel<<<B_*4, 128>>>(pHM2n, HM_);

    // ---- classifier ----
    final_kernel<<<1, 256>>>(Wc, out);
}

// round 3
// speedup vs baseline: 2.1293x; 1.6462x over previous
#include <cuda_runtime.h>
#include <cstdint>

#define P_ 4096
#define PN_ 32
#define PE_ 128
#define B_ 4
#define M_ 1024
#define ME_ 16384
#define IN_ 64
#define HP_ 256
#define HP4_ 64
#define RD_ 256
#define HM_ 512
#define OUT_ 16
#define RTOT_ (IN_+HP_+HP4_)   // 384
#define EPS_ 1e-5f
#define SLOPE_ 0.01f

// ---------------- scratch ----------------
__device__ float g_Xa [(size_t)P_*PN_*IN_];    // pre-aggregated X  [131072,64]
__device__ float g_W  [(size_t)P_*PN_*PN_];    // dense norm adjacency per patch
__device__ float g_H1 [(size_t)P_*PN_*HP_];    // conv1 activated [131072,256]
__device__ float g_H2 [(size_t)P_*PN_*HP4_];   // conv2 pre-agg   [131072,64]
__device__ float g_R  [(size_t)P_*RTOT_];      // readout concat  [4096,384]
__device__ float g_E  [(size_t)P_*RD_];        // patch embed     [4096,256]
__device__ float g_NF [(size_t)P_*RD_];        // node feats      [4096,256]
__device__ float g_NFa[(size_t)B_*M_*RD_];     // mesh-agg node feats
__device__ float g_HM [(size_t)B_*M_*HM_];     // mesh conv1 pre-norm
__device__ float g_HMn[(size_t)B_*M_*HM_];     // mesh h1 activated
__device__ float g_HMa[(size_t)B_*M_*HM_];     // mesh-agg h1
__device__ float g_HM2[(size_t)B_*M_*HM_];     // mesh conv2 pre-norm
__device__ float g_mouts[B_*M_], g_mins[B_*M_];
__device__ int   g_cnt_in[B_*M_], g_rowstart[B_*M_], g_cursor[B_*M_];
__device__ int   g_srcs[B_*ME_];
__device__ float g_wgt [B_*ME_];
__device__ float g_block[B_*2*HM_];

// ---------------- tf32 helpers ----------------
__device__ __forceinline__ uint32_t f2tf32(float f) {
    uint32_t u;
    asm("cvt.rna.tf32.f32 %0, %1;" : "=r"(u) : "f"(f));
    return u;
}
__device__ __forceinline__ uint32_t smem_u32(const void* p) {
    return static_cast<uint32_t>(__cvta_generic_to_shared(p));
}
__device__ __forceinline__ void ldsm_x4(uint32_t& r0, uint32_t& r1,
                                        uint32_t& r2, uint32_t& r3, uint32_t addr) {
    asm volatile("ldmatrix.sync.aligned.m8n8.x4.shared.b16 {%0,%1,%2,%3}, [%4];\n"
                 : "=r"(r0), "=r"(r1), "=r"(r2), "=r"(r3) : "r"(addr));
}
__device__ __forceinline__ void mma_tf32(float* c, const uint32_t* a,
                                         uint32_t b0, uint32_t b1) {
    asm volatile(
        "mma.sync.aligned.m16n8k8.row.col.f32.tf32.tf32.f32 "
        "{%0,%1,%2,%3}, {%4,%5,%6,%7}, {%8,%9}, {%0,%1,%2,%3};\n"
        : "+f"(c[0]), "+f"(c[1]), "+f"(c[2]), "+f"(c[3])
        : "r"(a[0]), "r"(a[1]), "r"(a[2]), "r"(a[3]), "r"(b0), "r"(b1));
}
__device__ __forceinline__ float red8(float v) {
    v += __shfl_xor_sync(0xffffffffu, v, 4);
    v += __shfl_xor_sync(0xffffffffu, v, 8);
    v += __shfl_xor_sync(0xffffffffu, v, 16);
    return v;
}
__device__ __forceinline__ float lrelu_f(float x) { return x >= 0.f ? x : SLOPE_*x; }

// ---------------- plain tf32 GEMM ----------------
template<int BM, int BN>
__global__ void __launch_bounds__(256)
gemm_tf32(const float* __restrict__ A, const float* __restrict__ B,
          float* __restrict__ C, int Mdim, int Ndim, int Kdim)
{
    constexpr int BK  = 32;
    constexpr int WM  = 32;
    constexpr int WN  = BN / 2;
    constexpr int MT  = WM / 16;
    constexpr int NT  = WN / 8;
    constexpr int ASR = BK + 4;
    constexpr int BSR = BN + 8;
    constexpr int ASZ = BM * ASR;
    constexpr int BSZ = BK * BSR;
    constexpr int ALD = BM * BK / 4 / 256;
    constexpr int BLD = BK * BN / 4 / 256;

    extern __shared__ uint32_t sm_[];
    uint32_t* As = sm_;
    uint32_t* Bs = sm_ + 2 * ASZ;

    const int tid  = threadIdx.x;
    const int lane = tid & 31;
    const int wid  = tid >> 5;
    const int nblk = Ndim / BN;
    const int bx = blockIdx.x % nblk;
    const int by = blockIdx.x / nblk;
    const float* Ab = A + (size_t)by * BM * Kdim;
    const float* Bb = B + (size_t)bx * BN;

    const int wm = (wid >> 1) * WM;
    const int wn = (wid & 1) * WN;

    float c[MT][NT][4];
    #pragma unroll
    for (int i = 0; i < MT; i++)
        #pragma unroll
        for (int j = 0; j < NT; j++)
            #pragma unroll
            for (int q = 0; q < 4; q++) c[i][j][q] = 0.f;

    float4 pa[ALD], pb[BLD];

    auto ldgA = [&](int k0) {
        #pragma unroll
        for (int i = 0; i < ALD; i++) {
            int lin = tid + i * 256;
            int row = lin >> 3;
            int kq  = lin & 7;
            pa[i] = *(const float4*)(Ab + (size_t)row * Kdim + k0 + kq * 4);
        }
    };
    auto ldgB = [&](int k0) {
        #pragma unroll
        for (int i = 0; i < BLD; i++) {
            int lin = tid + i * 256;
            int kr = lin / (BN / 4);
            int nq = lin % (BN / 4);
            pb[i] = *(const float4*)(Bb + (size_t)(k0 + kr) * Ndim + nq * 4);
        }
    };
    auto stsA = [&](int buf) {
        uint32_t* base = As + buf * ASZ;
        #pragma unroll
        for (int i = 0; i < ALD; i++) {
            int lin = tid + i * 256;
            int row = lin >> 3;
            int kq  = lin & 7;
            uint4 v = make_uint4(f2tf32(pa[i].x), f2tf32(pa[i].y),
                                 f2tf32(pa[i].z), f2tf32(pa[i].w));
            *(uint4*)(base + row * ASR + kq * 4) = v;
        }
    };
    auto stsB = [&](int buf) {
        uint32_t* base = Bs + buf * BSZ;
        #pragma unroll
        for (int i = 0; i < BLD; i++) {
            int lin = tid + i * 256;
            int kr = lin / (BN / 4);
            int nq = lin % (BN / 4);
            uint4 v = make_uint4(f2tf32(pb[i].x), f2tf32(pb[i].y),
                                 f2tf32(pb[i].z), f2tf32(pb[i].w));
            *(uint4*)(base + kr * BSR + nq * 4) = v;
        }
    };

    const int arow = wm + (lane & 15);
    const int acol = (lane >> 4) * 4;
    const int bn0  = wn + (lane >> 2);
    const int bk0  = lane & 3;

    auto compute = [&](int buf) {
        uint32_t* Abs = As + buf * ASZ;
        uint32_t* Bbs = Bs + buf * BSZ;
        #pragma unroll
        for (int ks = 0; ks < 4; ks++) {
            uint32_t a[MT][4];
            #pragma unroll
            for (int i = 0; i < MT; i++) {
                uint32_t addr = smem_u32(Abs + (arow + i * 16) * ASR + ks * 8 + acol);
                ldsm_x4(a[i][0], a[i][1], a[i][2], a[i][3], addr);
            }
            uint32_t b0[NT], b1[NT];
            #pragma unroll
            for (int j = 0; j < NT; j++) {
                b0[j] = Bbs[(ks * 8 + bk0) * BSR + bn0 + j * 8];
                b1[j] = Bbs[(ks * 8 + 4 + bk0) * BSR + bn0 + j * 8];
            }
            #pragma unroll
            for (int i = 0; i < MT; i++)
                #pragma unroll
                for (int j = 0; j < NT; j++)
                    mma_tf32(c[i][j], a[i], b0[j], b1[j]);
        }
    };

    const int NKT = Kdim / BK;
    ldgA(0); ldgB(0);
    stsA(0); stsB(0);
    __syncthreads();
    for (int kt = 0; kt < NKT; kt++) {
        if (kt + 1 < NKT) { ldgA((kt + 1) * BK); ldgB((kt + 1) * BK); }
        compute(kt & 1);
        if (kt + 1 < NKT) { stsA((kt + 1) & 1); stsB((kt + 1) & 1); }
        __syncthreads();
    }

    float* Cb = C + (size_t)(by * BM + wm) * Ndim + bx * BN + wn;
    const int r0 = lane >> 2;
    const int c0 = (lane & 3) * 2;
    #pragma unroll
    for (int i = 0; i < MT; i++)
        #pragma unroll
        for (int j = 0; j < NT; j++) {
            *(float2*)(Cb + (size_t)(i * 16 + r0) * Ndim + j * 8 + c0) =
                make_float2(c[i][j][0], c[i][j][1]);
            *(float2*)(Cb + (size_t)(i * 16 + r0 + 8) * Ndim + j * 8 + c0) =
                make_float2(c[i][j][2], c[i][j][3]);
        }
}

// -------- conv1 GEMM with fused GraphNorm + lrelu + readout epilogue -------
// BM=128 (= 4 patches of 32 rows), BN=128. Each warp-row (wm) = one patch.
__global__ void __launch_bounds__(256)
gemm_tf32_gn(const float* __restrict__ A, const float* __restrict__ B,
             float* __restrict__ C, int Mdim, int Ndim, int Kdim,
             const float* __restrict__ gamma, const float* __restrict__ beta,
             const float* __restrict__ alpha, int r_off)
{
    constexpr int BM = 128, BN = 128;
    constexpr int BK  = 32;
    constexpr int WM  = 32;
    constexpr int WN  = BN / 2;
    constexpr int MT  = 2;
    constexpr int NT  = WN / 8;      // 8
    constexpr int ASR = BK + 4;
    constexpr int BSR = BN + 8;
    constexpr int ASZ = BM * ASR;
    constexpr int BSZ = BK * BSR;
    constexpr int ALD = BM * BK / 4 / 256;
    constexpr int BLD = BK * BN / 4 / 256;

    extern __shared__ uint32_t sm_[];
    uint32_t* As = sm_;
    uint32_t* Bs = sm_ + 2 * ASZ;

    const int tid  = threadIdx.x;
    const int lane = tid & 31;
    const int wid  = tid >> 5;
    const int nblk = Ndim / BN;
    const int bx = blockIdx.x % nblk;
    const int by = blockIdx.x / nblk;
    const float* Ab = A + (size_t)by * BM * Kdim;
    const float* Bb = B + (size_t)bx * BN;

    const int wm = (wid >> 1) * WM;
    const int wn = (wid & 1) * WN;

    float c[MT][NT][4];
    #pragma unroll
    for (int i = 0; i < MT; i++)
        #pragma unroll
        for (int j = 0; j < NT; j++)
            #pragma unroll
            for (int q = 0; q < 4; q++) c[i][j][q] = 0.f;

    float4 pa[ALD], pb[BLD];

    auto ldgA = [&](int k0) {
        #pragma unroll
        for (int i = 0; i < ALD; i++) {
            int lin = tid + i * 256;
            int row = lin >> 3;
            int kq  = lin & 7;
            pa[i] = *(const float4*)(Ab + (size_t)row * Kdim + k0 + kq * 4);
        }
    };
    auto ldgB = [&](int k0) {
        #pragma unroll
        for (int i = 0; i < BLD; i++) {
            int lin = tid + i * 256;
            int kr = lin / (BN / 4);
            int nq = lin % (BN / 4);
            pb[i] = *(const float4*)(Bb + (size_t)(k0 + kr) * Ndim + nq * 4);
        }
    };
    auto stsA = [&](int buf) {
        uint32_t* base = As + buf * ASZ;
        #pragma unroll
        for (int i = 0; i < ALD; i++) {
            int lin = tid + i * 256;
            int row = lin >> 3;
            int kq  = lin & 7;
            uint4 v = make_uint4(f2tf32(pa[i].x), f2tf32(pa[i].y),
                                 f2tf32(pa[i].z), f2tf32(pa[i].w));
            *(uint4*)(base + row * ASR + kq * 4) = v;
        }
    };
    auto stsB = [&](int buf) {
        uint32_t* base = Bs + buf * BSZ;
        #pragma unroll
        for (int i = 0; i < BLD; i++) {
            int lin = tid + i * 256;
            int kr = lin / (BN / 4);
            int nq = lin % (BN / 4);
            uint4 v = make_uint4(f2tf32(pb[i].x), f2tf32(pb[i].y),
                                 f2tf32(pb[i].z), f2tf32(pb[i].w));
            *(uint4*)(base + kr * BSR + nq * 4) = v;
        }
    };

    const int arow = wm + (lane & 15);
    const int acol = (lane >> 4) * 4;
    const int bn0  = wn + (lane >> 2);
    const int bk0  = lane & 3;

    auto compute = [&](int buf) {
        uint32_t* Abs = As + buf * ASZ;
        uint32_t* Bbs = Bs + buf * BSZ;
        #pragma unroll
        for (int ks = 0; ks < 4; ks++) {
            uint32_t a[MT][4];
            #pragma unroll
            for (int i = 0; i < MT; i++) {
                uint32_t addr = smem_u32(Abs + (arow + i * 16) * ASR + ks * 8 + acol);
                ldsm_x4(a[i][0], a[i][1], a[i][2], a[i][3], addr);
            }
            uint32_t b0[NT], b1[NT];
            #pragma unroll
            for (int j = 0; j < NT; j++) {
                b0[j] = Bbs[(ks * 8 + bk0) * BSR + bn0 + j * 8];
                b1[j] = Bbs[(ks * 8 + 4 + bk0) * BSR + bn0 + j * 8];
            }
            #pragma unroll
            for (int i = 0; i < MT; i++)
                #pragma unroll
                for (int j = 0; j < NT; j++)
                    mma_tf32(c[i][j], a[i], b0[j], b1[j]);
        }
    };

    const int NKT = Kdim / BK;
    ldgA(0); ldgB(0);
    stsA(0); stsB(0);
    __syncthreads();
    for (int kt = 0; kt < NKT; kt++) {
        if (kt + 1 < NKT) { ldgA((kt + 1) * BK); ldgB((kt + 1) * BK); }
        compute(kt & 1);
        if (kt + 1 < NKT) { stsA((kt + 1) & 1); stsB((kt + 1) & 1); }
        __syncthreads();
    }

    // ---- fused GraphNorm + lrelu + readout epilogue ----
    // This warp holds one full patch (32 rows) x 64 cols. Per column:
    // vals col a: c[i][j][0], c[i][j][2]; col b: c[i][j][1], c[i][j][3]
    const int pat = by * 4 + (wid >> 1);
    const int r0 = lane >> 2;
    const int c0 = (lane & 3) * 2;
    const float inv32 = 1.f / 32.f;
    float* Cb = C + (size_t)(by * BM + wm) * Ndim + bx * BN + wn;

    #pragma unroll
    for (int j = 0; j < NT; j++) {
        int ca = bx * BN + wn + j * 8 + c0;
        float va0 = c[0][j][0], va1 = c[0][j][2], va2 = c[1][j][0], va3 = c[1][j][2];
        float vb0 = c[0][j][1], vb1 = c[0][j][3], vb2 = c[1][j][1], vb3 = c[1][j][3];
        float ma = red8(va0+va1+va2+va3) * inv32;
        float mb = red8(vb0+vb1+vb2+vb3) * inv32;
        float ama = __ldg(&alpha[ca])   * ma;
        float amb = __ldg(&alpha[ca+1]) * mb;
        float da0=va0-ama, da1=va1-ama, da2=va2-ama, da3=va3-ama;
        float db0=vb0-amb, db1=vb1-amb, db2=vb2-amb, db3=vb3-amb;
        float qa = red8(da0*da0+da1*da1+da2*da2+da3*da3);
        float qb = red8(db0*db0+db1*db1+db2*db2+db3*db3);
        float ia = rsqrtf(qa*inv32 + EPS_);
        float ib = rsqrtf(qb*inv32 + EPS_);
        float ga = __ldg(&gamma[ca]),   ba = __ldg(&beta[ca]);
        float gb = __ldg(&gamma[ca+1]), bb = __ldg(&beta[ca+1]);
        float ha0 = lrelu_f(ga*da0*ia + ba), ha1 = lrelu_f(ga*da1*ia + ba);
        float ha2 = lrelu_f(ga*da2*ia + ba), ha3 = lrelu_f(ga*da3*ia + ba);
        float hb0 = lrelu_f(gb*db0*ib + bb), hb1 = lrelu_f(gb*db1*ib + bb);
        float hb2 = lrelu_f(gb*db2*ib + bb), hb3 = lrelu_f(gb*db3*ib + bb);
        // store H1 (rows r0, r0+8, r0+16, r0+24)
        *(float2*)(Cb + (size_t)(r0)      * Ndim + j * 8 + c0) = make_float2(ha0, hb0);
        *(float2*)(Cb + (size_t)(r0 + 8)  * Ndim + j * 8 + c0) = make_float2(ha1, hb1);
        *(float2*)(Cb + (size_t)(r0 + 16) * Ndim + j * 8 + c0) = make_float2(ha2, hb2);
        *(float2*)(Cb + (size_t)(r0 + 24) * Ndim + j * 8 + c0) = make_float2(ha3, hb3);
        // readout: mean over 32 rows
        float ra = red8(ha0+ha1+ha2+ha3) * inv32;
        float rb = red8(hb0+hb1+hb2+hb3) * inv32;
        if (r0 == 0) {
            g_R[(size_t)pat*RTOT_ + r_off + ca]     = ra;
            g_R[(size_t)pat*RTOT_ + r_off + ca + 1] = rb;
        }
    }
}

// ---------------- patch pre: dense adjacency + Xa = W@X + r0 ---------------
__global__ void __launch_bounds__(256)
k_patch_pre(const float* __restrict__ feats, const int* __restrict__ src,
            const int* __restrict__ dst, const float* __restrict__ ew)
{
    int p = blockIdx.x, t = threadIdx.x;            // 256 threads
    __shared__ float Xs[PN_*IN_];                    // 32x64
    __shared__ float Wsh[PN_*PN_];                   // 32x32
    __shared__ float outs[PN_], ins[PN_];
    __shared__ int   cnto[PN_], cnti[PN_];

    const float4* f4 = (const float4*)(feats + (size_t)p*PN_*IN_);
    ((float4*)Xs)[t]       = f4[t];
    ((float4*)Xs)[t + 256] = f4[t + 256];
    if (t < PN_) { cnto[t]=0; cnti[t]=0; }
    #pragma unroll
    for (int i=0;i<4;i++) Wsh[t + 256*i] = 0.f;
    __syncthreads();

    if (t < PE_) {
        int s = src[p*PE_+t], d = dst[p*PE_+t];
        atomicAdd(&Wsh[d*PN_+s], ew[p*PE_+t]);
        atomicAdd(&cnto[s],1);
        atomicAdd(&cnti[d],1);
    }
    __syncthreads();
    if (t < PN_) {
        outs[t] = rsqrtf(fmaxf((float)cnto[t],1.f));
        ins[t]  = rsqrtf(fmaxf((float)cnti[t],1.f));
    }
    __syncthreads();
    #pragma unroll
    for (int i=0;i<4;i++) {
        int idx = t + 256*i;
        float w = Wsh[idx] * ins[idx>>5] * outs[idx&31];
        Wsh[idx] = w;
        g_W[(size_t)p*PN_*PN_ + idx] = w;
    }
    __syncthreads();

    int col = t & 63, dq = t >> 6;                   // 64 cols x 4 d-groups
    float x[PN_];
    #pragma unroll
    for (int s=0;s<PN_;s++) x[s] = Xs[s*IN_ + col];
    if (dq == 0) {
        float s1 = 0.f;
        #pragma unroll
        for (int s=0;s<PN_;s++) s1 += x[s];
        g_R[(size_t)p*RTOT_ + col] = s1 * (1.f/PN_);
    }
    #pragma unroll
    for (int dd=0;dd<8;dd++) {
        int d = dq*8 + dd;
        const float4* w4 = (const float4*)&Wsh[d*PN_];
        float acc = 0.f;
        #pragma unroll
        for (int s4=0;s4<8;s4++) {
            float4 w = w4[s4];
            acc += w.x*x[4*s4] + w.y*x[4*s4+1] + w.z*x[4*s4+2] + w.w*x[4*s4+3];
        }
        g_Xa[(size_t)(p*PN_ + d)*IN_ + col] = acc;
    }
}

// ------- patch post: agg(H2pre) + GraphNorm + lrelu + r2 readout -----------
__global__ void __launch_bounds__(64)
k_patch_post(const float* __restrict__ H2pre,
             const float* __restrict__ gamma, const float* __restrict__ beta,
             const float* __restrict__ alpha)
{
    int p = blockIdx.x, j = threadIdx.x;            // 64 threads = 64 cols
    __shared__ float Wsh[PN_*PN_];
    #pragma unroll
    for (int i=0;i<16;i++) Wsh[j + 64*i] = g_W[(size_t)p*PN_*PN_ + j + 64*i];

    float h[PN_];
    const float* Hp = H2pre + (size_t)p*PN_*HP4_;
    #pragma unroll
    for (int s=0;s<PN_;s++) h[s] = Hp[s*HP4_ + j];
    __syncthreads();

    float xv[PN_];
    #pragma unroll
    for (int d=0;d<PN_;d++) {
        const float4* w4 = (const float4*)&Wsh[d*PN_];
        float acc = 0.f;
        #pragma unroll
        for (int s4=0;s4<8;s4++) {
            float4 w = w4[s4];
            acc += w.x*h[4*s4] + w.y*h[4*s4+1] + w.z*h[4*s4+2] + w.w*h[4*s4+3];
        }
        xv[d] = acc;
    }
    float s1 = 0.f;
    #pragma unroll
    for (int d=0;d<PN_;d++) s1 += xv[d];
    float am = alpha[j] * s1 * (1.f/PN_);
    float s2 = 0.f;
    #pragma unroll
    for (int d=0;d<PN_;d++) { float u = xv[d]-am; s2 += u*u; }
    float istd = rsqrtf(s2*(1.f/PN_) + EPS_);
    float g = gamma[j], bb = beta[j];
    float rs = 0.f;
    #pragma unroll
    for (int d=0;d<PN_;d++) rs += lrelu_f(g*(xv[d]-am)*istd + bb);
    g_R[(size_t)p*RTOT_ + IN_ + HP_ + j] = rs*(1.f/PN_);
}

// ---------------- instance norm + lrelu ----------------
__global__ void inorm_kernel(const float* __restrict__ E, float* __restrict__ NF)
{
    int p = blockIdx.x, j = threadIdx.x;            // 256 threads
    __shared__ float sm[16];
    float v = E[(size_t)p*RD_ + j];

    float s1 = v;
    #pragma unroll
    for (int o=16;o>0;o>>=1) s1 += __shfl_xor_sync(0xffffffffu, s1, o);
    if ((j&31)==0) sm[j>>5] = s1;
    __syncthreads();
    if (j < 32) {
        float x = (j<8)? sm[j] : 0.f;
        #pragma unroll
        for (int o=4;o>0;o>>=1) x += __shfl_xor_sync(0xffffffffu, x, o);
        if (j==0) sm[8] = x;
    }
    __syncthreads();
    float mu = sm[8]*(1.f/RD_);
    float d  = v - mu;

    float s2 = d*d;
    #pragma unroll
    for (int o=16;o>0;o>>=1) s2 += __shfl_xor_sync(0xffffffffu, s2, o);
    if ((j&31)==0) sm[j>>5] = s2;
    __syncthreads();
    if (j < 32) {
        float x = (j<8)? sm[j] : 0.f;
        #pragma unroll
        for (int o=4;o>0;o>>=1) x += __shfl_xor_sync(0xffffffffu, x, o);
        if (j==0) sm[9] = x;
    }
    __syncthreads();
    float var = sm[9]*(1.f/RD_);
    float y = d * rsqrtf(var + EPS_);
    NF[(size_t)p*RD_ + j] = y>=0.f ? y : SLOPE_*y;
}

// ---------------- mesh glue -----------------------------------------------
__global__ void mdeg_kernel(const int* __restrict__ msrc,
                            const int* __restrict__ mdst)
{
    int b = blockIdx.x, t = threadIdx.x;            // 1024 threads
    __shared__ int co[M_], ci[M_];
    co[t]=0; ci[t]=0;
    __syncthreads();
    const int* sp = msrc + b*ME_;
    const int* dp = mdst + b*ME_;
    for (int e=t;e<ME_;e+=M_) {
        atomicAdd(&co[sp[e]],1);
        atomicAdd(&ci[dp[e]],1);
    }
    __syncthreads();
    g_mouts[b*M_+t] = rsqrtf(fmaxf((float)co[t],1.f));
    g_mins [b*M_+t] = rsqrtf(fmaxf((float)ci[t],1.f));
    g_cnt_in[b*M_+t] = ci[t];
}

__global__ void mscan_kernel()
{
    int b = blockIdx.x, t = threadIdx.x;            // 1024 threads
    __shared__ int s[M_];
    int orig = g_cnt_in[b*M_+t];
    s[t] = orig;
    __syncthreads();
    for (int o=1;o<M_;o<<=1) {
        int u = (t>=o)? s[t-o] : 0;
        __syncthreads();
        s[t] += u;
        __syncthreads();
    }
    int st = s[t] - orig;
    g_rowstart[b*M_+t] = st;
    g_cursor  [b*M_+t] = st;
}

__global__ void mbucket_kernel(const int* __restrict__ msrc,
                               const int* __restrict__ mdst,
                               const float* __restrict__ mew)
{
    int eg = blockIdx.x*256 + threadIdx.x;
    if (eg >= B_*ME_) return;
    int b = eg >> 14;
    int s = msrc[eg], d = mdst[eg];
    int pos = atomicAdd(&g_cursor[b*M_+d], 1);
    g_srcs[b*ME_+pos] = s;
    g_wgt [b*ME_+pos] = mew[eg] * g_mouts[b*M_+s];
}

// gather aggregation with fused ins scaling; C = channel width
template<int C>
__global__ void magg_k(const float* __restrict__ H, float* __restrict__ AGG)
{
    int node = blockIdx.x;                           // 0..4095
    int b = node >> 10;
    int n = node & (M_-1);
    int c = blockIdx.y*128 + threadIdx.x;
    int beg = g_rowstart[node];
    int end = (n==M_-1) ? ME_ : g_rowstart[node+1];
    const int*   sarr = g_srcs + b*ME_;
    const float* warr = g_wgt  + b*ME_;
    float acc = 0.f;
    for (int i=beg;i<end;i++)
        acc += H[(size_t)(b*M_ + sarr[i])*C + c] * warr[i];
    AGG[(size_t)node*C + c] = acc * g_mins[node];
}

// fused GraphNorm stats + norm + lrelu + readout over one mesh column
template<bool WRITE>
__global__ void k_mesh_norm(const float* __restrict__ Hpre,
                            const float* __restrict__ gamma,
                            const float* __restrict__ beta,
                            const float* __restrict__ alpha,
                            float* __restrict__ Hn, int off)
{
    int b = blockIdx.x >> 2;
    int c = (blockIdx.x & 3)*128 + threadIdx.x;
    const float* A = Hpre + (size_t)b*M_*HM_;
    float s1 = 0.f, s2 = 0.f;
    #pragma unroll 4
    for (int r=0;r<M_;r++) { float v = A[(size_t)r*HM_+c]; s1+=v; s2+=v*v; }
    float mean = s1*(1.f/M_);
    float am = alpha[c]*mean;
    float var = s2*(1.f/M_) - 2.f*am*mean + am*am;
    float istd = rsqrtf(fmaxf(var,0.f) + EPS_);
    float g = gamma[c], bb = beta[c];
    float rs = 0.f;
    #pragma unroll 4
    for (int r=0;r<M_;r++) {
        float v = A[(size_t)r*HM_+c];
        float h = lrelu_f(g*(v-am)*istd + bb);
        if (WRITE) Hn[(size_t)(b*M_+r)*HM_ + c] = h;
        rs += h;
    }
    g_block[b*2*HM_ + off + c] = rs*(1.f/M_);
}

__global__ void final_kernel(const float* __restrict__ Wc, float* __restrict__ out)
{
    int t = threadIdx.x;                             // 256 threads
    float acc[OUT_];
    #pragma unroll
    for (int o=0;o<OUT_;o++) acc[o]=0.f;
    for (int i=t;i<B_*2*HM_;i+=256) {
        float v = lrelu_f(g_block[i]);
        #pragma unroll
        for (int o=0;o<OUT_;o++) acc[o] += v*Wc[(size_t)i*OUT_+o];
    }
    __shared__ float red[OUT_][256];
    #pragma unroll
    for (int o=0;o<OUT_;o++) red[o][t]=acc[o];
    __syncthreads();
    for (int s=128;s>0;s>>=1) {
        if (t<s) {
            #pragma unroll
            for (int o=0;o<OUT_;o++) red[o][t]+=red[o][t+s];
        }
        __syncthreads();
    }
    if (t<OUT_) out[t]=red[t][0];
}

// ---------------- launcher -------------------------------------------------
extern "C" void kernel_launch(void* const* d_in, const int* in_sizes, int n_in,
                              void* d_out, int out_size)
{
    (void)in_sizes; (void)n_in; (void)out_size;
    const float* feats = (const float*)d_in[0];
    const int*   psrc  = (const int*)  d_in[1];
    const int*   pdst  = (const int*)  d_in[2];
    const float* pew   = (const float*)d_in[3];
    const int*   msrc  = (const int*)  d_in[4];
    const int*   mdst  = (const int*)  d_in[5];
    const float* mew   = (const float*)d_in[6];
    const float* Wp1   = (const float*)d_in[7];
    const float* Wp2   = (const float*)d_in[8];
    const float* W_emb = (const float*)d_in[9];
    const float* gp1_g = (const float*)d_in[10];
    const float* gp1_b = (const float*)d_in[11];
    const float* gp1_a = (const float*)d_in[12];
    const float* gp2_g = (const float*)d_in[13];
    const float* gp2_b = (const float*)d_in[14];
    const float* gp2_a = (const float*)d_in[15];
    const float* gm1_g = (const float*)d_in[16];
    const float* gm1_b = (const float*)d_in[17];
    const float* gm1_a = (const float*)d_in[18];
    const float* gm2_g = (const float*)d_in[19];
    const float* gm2_b = (const float*)d_in[20];
    const float* gm2_a = (const float*)d_in[21];
    const float* Wm1   = (const float*)d_in[22];
    const float* Wm2   = (const float*)d_in[23];
    const float* Wc    = (const float*)d_in[24];
    float* out = (float*)d_out;

    float *pXa,*pH1,*pH2,*pR,*pE,*pNF,*pNFa,*pHM,*pHMn,*pHMa,*pHM2;
    cudaGetSymbolAddress((void**)&pXa,  g_Xa);
    cudaGetSymbolAddress((void**)&pH1,  g_H1);
    cudaGetSymbolAddress((void**)&pH2,  g_H2);
    cudaGetSymbolAddress((void**)&pR,   g_R);
    cudaGetSymbolAddress((void**)&pE,   g_E);
    cudaGetSymbolAddress((void**)&pNF,  g_NF);
    cudaGetSymbolAddress((void**)&pNFa, g_NFa);
    cudaGetSymbolAddress((void**)&pHM,  g_HM);
    cudaGetSymbolAddress((void**)&pHMn, g_HMn);
    cudaGetSymbolAddress((void**)&pHMa, g_HMa);
    cudaGetSymbolAddress((void**)&pHM2, g_HM2);

    const int SM128 = (2*128*36 + 2*32*136) * 4;   // 71680 B
    const int SM64  = (2*128*36 + 2*32*72)  * 4;   // 55296 B
    cudaFuncSetAttribute(gemm_tf32<128,128>,
                         cudaFuncAttributeMaxDynamicSharedMemorySize, SM128);
    cudaFuncSetAttribute(gemm_tf32<128,64>,
                         cudaFuncAttributeMaxDynamicSharedMemorySize, SM64);
    cudaFuncSetAttribute(gemm_tf32_gn,
                         cudaFuncAttributeMaxDynamicSharedMemorySize, SM128);

    // ---- patch phase ----
    k_patch_pre<<<P_, 256>>>(feats, psrc, pdst, pew);
    gemm_tf32_gn<<<(P_*PN_/128)*(HP_/128), 256, SM128>>>(
        pXa, Wp1, pH1, P_*PN_, HP_, IN_, gp1_g, gp1_b, gp1_a, IN_);
    gemm_tf32<128,64><<<(P_*PN_/128)*(HP4_/64), 256, SM64>>>(
        pH1, Wp2, pH2, P_*PN_, HP4_, HP_);
    k_patch_post<<<P_, 64>>>(pH2, gp2_g, gp2_b, gp2_a);
    gemm_tf32<128,128><<<(P_/128)*(RD_/128), 256, SM128>>>(
        pR, W_emb, pE, P_, RD_, RTOT_);
    inorm_kernel<<<P_, RD_>>>(pE, pNF);

    // ---- mesh CSR build ----
    mdeg_kernel<<<B_, M_>>>(msrc, mdst);
    mscan_kernel<<<B_, M_>>>();
    mbucket_kernel<<<B_*ME_/256, 256>>>(msrc, mdst, mew);

    // ---- mesh layer 1 (pre-aggregate in 256-dim) ----
    magg_k<RD_><<<dim3(B_*M_, RD_/128), 128>>>(pNF, pNFa);
    gemm_tf32<128,128><<<(B_*M_/128)*(HM_/128), 256, SM128>>>(
        pNFa, Wm1, pHM, B_*M_, HM_, RD_);
    k_mesh_norm<true><<<B_*4, 128>>>(pHM, gm1_g, gm1_b, gm1_a, pHMn, 0);

    // ---- mesh layer 2 ----
    magg_k<HM_><<<dim3(B_*M_, HM_/128), 128>>>(pHMn, pHMa);
    gemm_tf32<128,128><<<(B_*M_/128)*(HM_/128), 256, SM128>>>(
        pHMa, Wm2, pHM2, B_*M_, HM_, HM_);
    k_mesh_norm<false><<<B_*4, 128>>>(pHM2, gm2_g, gm2_b, gm2_a, nullptr, HM_);

    // ---- classifier ----
    final_kernel<<<1, 256>>>(Wc, out);
}

// round 4
// speedup vs baseline: 2.2163x; 1.0409x over previous
#include <cuda_runtime.h>
#include <cstdint>

#define P_ 4096
#define PN_ 32
#define PE_ 128
#define B_ 4
#define M_ 1024
#define ME_ 16384
#define IN_ 64
#define HP_ 256
#define HP4_ 64
#define RD_ 256
#define HM_ 512
#define OUT_ 16
#define RTOT_ (IN_+HP_+HP4_)   // 384
#define EPS_ 1e-5f
#define SLOPE_ 0.01f

// ---------------- scratch ----------------
__device__ float g_R  [(size_t)P_*RTOT_];      // readout concat  [4096,384]
__device__ float g_E  [(size_t)P_*RD_];        // patch embed     [4096,256]
__device__ float g_NF [(size_t)P_*RD_];        // node feats      [4096,256]
__device__ float g_NFa[(size_t)B_*M_*RD_];     // mesh-agg node feats
__device__ float g_HM [(size_t)B_*M_*HM_];     // mesh conv1 pre-norm
__device__ float g_HMn[(size_t)B_*M_*HM_];     // mesh h1 activated
__device__ float g_HMa[(size_t)B_*M_*HM_];     // mesh-agg h1
__device__ float g_HM2[(size_t)B_*M_*HM_];     // mesh conv2 pre-norm
__device__ float g_mouts[B_*M_], g_mins[B_*M_];
__device__ int   g_rowstart[B_*M_], g_cursor[B_*M_];
__device__ int   g_srcs[B_*ME_];
__device__ float g_wgt [B_*ME_];
__device__ float g_block[B_*2*HM_];

// ---------------- tf32 helpers ----------------
__device__ __forceinline__ uint32_t f2tf32(float f) {
    uint32_t u;
    asm("cvt.rna.tf32.f32 %0, %1;" : "=r"(u) : "f"(f));
    return u;
}
__device__ __forceinline__ uint32_t smem_u32(const void* p) {
    return static_cast<uint32_t>(__cvta_generic_to_shared(p));
}
__device__ __forceinline__ void ldsm_x4(uint32_t& r0, uint32_t& r1,
                                        uint32_t& r2, uint32_t& r3, uint32_t addr) {
    asm volatile("ldmatrix.sync.aligned.m8n8.x4.shared.b16 {%0,%1,%2,%3}, [%4];\n"
                 : "=r"(r0), "=r"(r1), "=r"(r2), "=r"(r3) : "r"(addr));
}
__device__ __forceinline__ void mma_tf32(float* c, const uint32_t* a,
                                         uint32_t b0, uint32_t b1) {
    asm volatile(
        "mma.sync.aligned.m16n8k8.row.col.f32.tf32.tf32.f32 "
        "{%0,%1,%2,%3}, {%4,%5,%6,%7}, {%8,%9}, {%0,%1,%2,%3};\n"
        : "+f"(c[0]), "+f"(c[1]), "+f"(c[2]), "+f"(c[3])
        : "r"(a[0]), "r"(a[1]), "r"(a[2]), "r"(a[3]), "r"(b0), "r"(b1));
}
__device__ __forceinline__ float red8(float v) {
    v += __shfl_xor_sync(0xffffffffu, v, 4);
    v += __shfl_xor_sync(0xffffffffu, v, 8);
    v += __shfl_xor_sync(0xffffffffu, v, 16);
    return v;
}
__device__ __forceinline__ float lrelu_f(float x) { return x >= 0.f ? x : SLOPE_*x; }

// ============== fused patch phase: one CTA = 2 patches =====================
// smem word layout (1 word = 4B), total 28416 words = 113664 B:
//  [0,2048)        Wsh  : 2 x 32x32 dense normalized adjacency (float)
//  [2048,2112)     outs : 2x32
//  [2112,2176)     ins  : 2x32
//  [2176,2304)     cnt  : 2x32 out-deg, 2x32 in-deg (int)
//  region2 [2304, 2304+9216):
//     Xs [64][68] float   (phase X)    | Bs2 [128][72] tf32 (conv2 B stage)
//     A1 [64][68] tf32 at +4352        |
//  region3 [11520, 11520+16896):
//     B1 [64][264] tf32 (Wp1) | As2 [64][260] tf32 (H1) | H2s [64][68] float
#define SMW_TOTAL 28416
#define SMB_PATCH (SMW_TOTAL*4)

__global__ void __launch_bounds__(256)
k_patch_all(const float* __restrict__ feats, const int* __restrict__ src,
            const int* __restrict__ dst, const float* __restrict__ ew,
            const float* __restrict__ Wp1, const float* __restrict__ Wp2,
            const float* __restrict__ g1g, const float* __restrict__ g1b,
            const float* __restrict__ g1a, const float* __restrict__ g2g,
            const float* __restrict__ g2b, const float* __restrict__ g2a)
{
    extern __shared__ uint32_t S[];
    float*    Wsh  = (float*)S;                  // 2048
    float*    outs = (float*)(S + 2048);         // 64
    float*    ins  = (float*)(S + 2112);         // 64
    int*      cnt  = (int*)  (S + 2176);         // 128
    float*    Xs   = (float*)(S + 2304);         // [64][68]
    uint32_t* A1   = S + 2304 + 4352;            // [64][68]
    uint32_t* Bs2  = S + 2304;                   // [128][72]
    uint32_t* B1   = S + 11520;                  // [64][264]
    uint32_t* As2  = S + 11520;                  // [64][260]
    float*    H2s  = (float*)(S + 11520);        // [64][68]

    const int t    = threadIdx.x;
    const int blk  = blockIdx.x;
    const int lane = t & 31;
    const int wid  = t >> 5;

    // ---- phase 0: zero W/cnt, load X, load Wp1 ----
    #pragma unroll
    for (int i = 0; i < 8; i++) Wsh[t + 256*i] = 0.f;
    if (t < 128) cnt[t] = 0;
    {   // feats rows [blk*64, +64), 64 cols -> Xs[row][col], pitch 68
        const float4* f4 = (const float4*)(feats + (size_t)blk*64*IN_);
        #pragma unroll
        for (int i = 0; i < 4; i++) {
            int lin = t + i*256;
            int lr = lin >> 4, cq = lin & 15;
            *(float4*)(Xs + lr*68 + cq*4) = f4[lin];
        }
        // Wp1 [64][256] -> B1 k-major pitch 264 (tf32)
        const float4* w4 = (const float4*)Wp1;
        #pragma unroll
        for (int i = 0; i < 16; i++) {
            int lin = t + i*256;
            int k = lin >> 6, nq = lin & 63;
            float4 v = w4[lin];
            *(uint4*)(B1 + k*264 + nq*4) =
                make_uint4(f2tf32(v.x), f2tf32(v.y), f2tf32(v.z), f2tf32(v.w));
        }
    }
    __syncthreads();

    // ---- phase 1: build dense normalized adjacency for 2 patches ----
    {
        int q = t >> 7, e = t & 127;
        int p = blk*2 + q;
        int s = src[p*PE_ + e], d = dst[p*PE_ + e];
        atomicAdd(&Wsh[q*1024 + d*PN_ + s], ew[p*PE_ + e]);
        atomicAdd(&cnt[q*PN_ + s], 1);            // out-degree
        atomicAdd(&cnt[64 + q*PN_ + d], 1);       // in-degree
    }
    __syncthreads();
    if (t < 64) {
        outs[t] = rsqrtf(fmaxf((float)cnt[t], 1.f));
        ins[t]  = rsqrtf(fmaxf((float)cnt[64 + t], 1.f));
    }
    __syncthreads();
    #pragma unroll
    for (int i = 0; i < 8; i++) {
        int idx = t + 256*i;
        int q = idx >> 10, rem = idx & 1023;
        int dn = rem >> 5, sn = rem & 31;
        Wsh[idx] *= ins[q*PN_ + dn] * outs[q*PN_ + sn];
    }
    __syncthreads();

    // ---- phase 2: Xa = W @ X (into A1 as tf32), r0 readout ----
    {
        int col = t & 63, dg = t >> 6;            // 4 d-groups of 8
        #pragma unroll
        for (int q = 0; q < 2; q++) {
            float x[PN_];
            #pragma unroll
            for (int s = 0; s < PN_; s++) x[s] = Xs[(q*32 + s)*68 + col];
            if (dg == 0) {
                float s1 = 0.f;
                #pragma unroll
                for (int s = 0; s < PN_; s++) s1 += x[s];
                g_R[(size_t)(blk*2 + q)*RTOT_ + col] = s1 * (1.f/PN_);
            }
            #pragma unroll
            for (int dd = 0; dd < 8; dd++) {
                int d = dg*8 + dd;
                const float* wrow = &Wsh[q*1024 + d*PN_];
                float acc = 0.f;
                #pragma unroll
                for (int s = 0; s < PN_; s++) acc += wrow[s] * x[s];
                A1[(q*32 + d)*68 + col] = f2tf32(acc);
            }
        }
    }
    __syncthreads();

    // ---- phase 3: conv1 mma: [64,64] @ [64,256] ----
    // warps: 2 rows x 4 cols; warp tile 32x64 (MT=2, NT=8)
    const int wm  = (wid >> 2) * 32;
    const int wn  = (wid & 3) * 64;
    const int arow = wm + (lane & 15);
    const int acol = (lane >> 4) * 4;
    const int bn0  = wn + (lane >> 2);
    const int bk0  = lane & 3;

    float c1[2][8][4];
    #pragma unroll
    for (int i = 0; i < 2; i++)
        #pragma unroll
        for (int j = 0; j < 8; j++)
            #pragma unroll
            for (int q = 0; q < 4; q++) c1[i][j][q] = 0.f;

    #pragma unroll
    for (int ks = 0; ks < 8; ks++) {
        uint32_t a[2][4];
        #pragma unroll
        for (int i = 0; i < 2; i++) {
            uint32_t addr = smem_u32(A1 + (arow + i*16)*68 + ks*8 + acol);
            ldsm_x4(a[i][0], a[i][1], a[i][2], a[i][3], addr);
        }
        uint32_t b0[8], b1v[8];
        #pragma unroll
        for (int j = 0; j < 8; j++) {
            b0[j]  = B1[(ks*8 + bk0)*264 + bn0 + j*8];
            b1v[j] = B1[(ks*8 + 4 + bk0)*264 + bn0 + j*8];
        }
        #pragma unroll
        for (int i = 0; i < 2; i++)
            #pragma unroll
            for (int j = 0; j < 8; j++)
                mma_tf32(c1[i][j], a[i], b0[j], b1v[j]);
    }
    __syncthreads();   // B1/A1 dead; As2 overlays B1

    // ---- phase 4: GraphNorm + lrelu + r1; H1 -> As2 (tf32) ----
    {
        const int pat = blk*2 + (wid >> 2);
        const int r0 = lane >> 2;
        const int c0 = (lane & 3) * 2;
        const float inv32 = 1.f / 32.f;
        #pragma unroll
        for (int j = 0; j < 8; j++) {
            int ca = wn + j*8 + c0;               // channel 0..255
            float va0=c1[0][j][0], va1=c1[0][j][2], va2=c1[1][j][0], va3=c1[1][j][2];
            float vb0=c1[0][j][1], vb1=c1[0][j][3], vb2=c1[1][j][1], vb3=c1[1][j][3];
            float ma = red8(va0+va1+va2+va3) * inv32;
            float mb = red8(vb0+vb1+vb2+vb3) * inv32;
            float ama = __ldg(&g1a[ca])   * ma;
            float amb = __ldg(&g1a[ca+1]) * mb;
            float da0=va0-ama, da1=va1-ama, da2=va2-ama, da3=va3-ama;
            float db0=vb0-amb, db1=vb1-amb, db2=vb2-amb, db3=vb3-amb;
            float qa = red8(da0*da0+da1*da1+da2*da2+da3*da3);
            float qb = red8(db0*db0+db1*db1+db2*db2+db3*db3);
            float ia = rsqrtf(qa*inv32 + EPS_);
            float ib = rsqrtf(qb*inv32 + EPS_);
            float ga = __ldg(&g1g[ca]),   ba = __ldg(&g1b[ca]);
            float gb = __ldg(&g1g[ca+1]), bb = __ldg(&g1b[ca+1]);
            float ha0=lrelu_f(ga*da0*ia+ba), ha1=lrelu_f(ga*da1*ia+ba);
            float ha2=lrelu_f(ga*da2*ia+ba), ha3=lrelu_f(ga*da3*ia+ba);
            float hb0=lrelu_f(gb*db0*ib+bb), hb1=lrelu_f(gb*db1*ib+bb);
            float hb2=lrelu_f(gb*db2*ib+bb), hb3=lrelu_f(gb*db3*ib+bb);
            uint32_t* dst0 = As2 + (wm + r0)*260 + wn + j*8 + c0;
            *(uint2*)(dst0)            = make_uint2(f2tf32(ha0), f2tf32(hb0));
            *(uint2*)(dst0 + 8*260)    = make_uint2(f2tf32(ha1), f2tf32(hb1));
            *(uint2*)(dst0 + 16*260)   = make_uint2(f2tf32(ha2), f2tf32(hb2));
            *(uint2*)(dst0 + 24*260)   = make_uint2(f2tf32(ha3), f2tf32(hb3));
            float ra = red8(ha0+ha1+ha2+ha3) * inv32;
            float rb = red8(hb0+hb1+hb2+hb3) * inv32;
            if (r0 == 0) {
                g_R[(size_t)pat*RTOT_ + IN_ + ca]     = ra;
                g_R[(size_t)pat*RTOT_ + IN_ + ca + 1] = rb;
            }
        }
    }
    __syncthreads();

    // ---- phase 5: conv2 mma: [64,256] @ [256,64], K in 2 chunks of 128 ----
    // warps: 2 rows x 4 cols; warp tile 32x16 (MT=2, NT=2)
    const int wn2  = (wid & 3) * 16;
    const int bn02 = wn2 + (lane >> 2);
    float c2[2][2][4];
    #pragma unroll
    for (int i = 0; i < 2; i++)
        #pragma unroll
        for (int j = 0; j < 2; j++)
            #pragma unroll
            for (int q = 0; q < 4; q++) c2[i][j][q] = 0.f;

    #pragma unroll
    for (int ch = 0; ch < 2; ch++) {
        // stage Wp2 chunk [128][64] -> Bs2 pitch 72 (overlays Xs/A1, both dead)
        const float4* w4 = (const float4*)(Wp2 + (size_t)ch*128*HP4_);
        #pragma unroll
        for (int i = 0; i < 8; i++) {
            int lin = t + i*256;
            int k = lin >> 4, nq = lin & 15;
            float4 v = w4[lin];
            *(uint4*)(Bs2 + k*72 + nq*4) =
                make_uint4(f2tf32(v.x), f2tf32(v.y), f2tf32(v.z), f2tf32(v.w));
        }
        __syncthreads();
        #pragma unroll
        for (int ks = 0; ks < 16; ks++) {
            uint32_t a[2][4];
            #pragma unroll
            for (int i = 0; i < 2; i++) {
                uint32_t addr = smem_u32(As2 + (arow + i*16)*260 + ch*128 + ks*8 + acol);
                ldsm_x4(a[i][0], a[i][1], a[i][2], a[i][3], addr);
            }
            uint32_t b0[2], b1v[2];
            #pragma unroll
            for (int j = 0; j < 2; j++) {
                b0[j]  = Bs2[(ks*8 + bk0)*72 + bn02 + j*8];
                b1v[j] = Bs2[(ks*8 + 4 + bk0)*72 + bn02 + j*8];
            }
            #pragma unroll
            for (int i = 0; i < 2; i++)
                #pragma unroll
                for (int j = 0; j < 2; j++)
                    mma_tf32(c2[i][j], a[i], b0[j], b1v[j]);
        }
        __syncthreads();   // before Bs2 reload / As2 overwrite
    }

    // ---- phase 6: H2 -> smem (overlays As2; all reads done) ----
    {
        const int r0 = lane >> 2;
        const int c0 = (lane & 3) * 2;
        #pragma unroll
        for (int i = 0; i < 2; i++)
            #pragma unroll
            for (int j = 0; j < 2; j++) {
                float* d0 = H2s + (wm + i*16 + r0)*68 + wn2 + j*8 + c0;
                *(float2*)(d0)        = make_float2(c2[i][j][0], c2[i][j][1]);
                *(float2*)(d0 + 8*68) = make_float2(c2[i][j][2], c2[i][j][3]);
            }
    }
    __syncthreads();

    // ---- phase 7: agg(W) + GraphNorm + lrelu + r2 readout ----
    if (t < 128) {
        int q = t >> 6, col = t & 63;
        float h[PN_];
        #pragma unroll
        for (int s = 0; s < PN_; s++) h[s] = H2s[(q*32 + s)*68 + col];
        float xv[PN_];
        #pragma unroll
        for (int d = 0; d < PN_; d++) {
            const float* wrow = &Wsh[q*1024 + d*PN_];
            float acc = 0.f;
            #pragma unroll
            for (int s = 0; s < PN_; s++) acc += wrow[s] * h[s];
            xv[d] = acc;
        }
        float s1 = 0.f;
        #pragma unroll
        for (int d = 0; d < PN_; d++) s1 += xv[d];
        float am = __ldg(&g2a[col]) * s1 * (1.f/PN_);
        float s2 = 0.f;
        #pragma unroll
        for (int d = 0; d < PN_; d++) { float u = xv[d]-am; s2 += u*u; }
        float istd = rsqrtf(s2*(1.f/PN_) + EPS_);
        float g = __ldg(&g2g[col]), bb = __ldg(&g2b[col]);
        float rs = 0.f;
        #pragma unroll
        for (int d = 0; d < PN_; d++) rs += lrelu_f(g*(xv[d]-am)*istd + bb);
        g_R[(size_t)(blk*2 + q)*RTOT_ + IN_ + HP_ + col] = rs*(1.f/PN_);
    }
}

// ---------------- plain tf32 GEMM (embed + mesh) ----------------
template<int BM, int BN>
__global__ void __launch_bounds__(256)
gemm_tf32(const float* __restrict__ A, const float* __restrict__ B,
          float* __restrict__ C, int Mdim, int Ndim, int Kdim)
{
    constexpr int BK  = 32;
    constexpr int WM  = 32;
    constexpr int WN  = BN / 2;
    constexpr int MT  = WM / 16;
    constexpr int NT  = WN / 8;
    constexpr int ASR = BK + 4;
    constexpr int BSR = BN + 8;
    constexpr int ASZ = BM * ASR;
    constexpr int BSZ = BK * BSR;
    constexpr int ALD = BM * BK / 4 / 256;
    constexpr int BLD = BK * BN / 4 / 256;

    extern __shared__ uint32_t sm_[];
    uint32_t* As = sm_;
    uint32_t* Bs = sm_ + 2 * ASZ;

    const int tid  = threadIdx.x;
    const int lane = tid & 31;
    const int wid  = tid >> 5;
    const int nblk = Ndim / BN;
    const int bx = blockIdx.x % nblk;
    const int by = blockIdx.x / nblk;
    const float* Ab = A + (size_t)by * BM * Kdim;
    const float* Bb = B + (size_t)bx * BN;

    const int wm = (wid >> 1) * WM;
    const int wn = (wid & 1) * WN;

    float c[MT][NT][4];
    #pragma unroll
    for (int i = 0; i < MT; i++)
        #pragma unroll
        for (int j = 0; j < NT; j++)
            #pragma unroll
            for (int q = 0; q < 4; q++) c[i][j][q] = 0.f;

    float4 pa[ALD], pb[BLD];

    auto ldgA = [&](int k0) {
        #pragma unroll
        for (int i = 0; i < ALD; i++) {
            int lin = tid + i * 256;
            int row = lin >> 3;
            int kq  = lin & 7;
            pa[i] = *(const float4*)(Ab + (size_t)row * Kdim + k0 + kq * 4);
        }
    };
    auto ldgB = [&](int k0) {
        #pragma unroll
        for (int i = 0; i < BLD; i++) {
            int lin = tid + i * 256;
            int kr = lin / (BN / 4);
            int nq = lin % (BN / 4);
            pb[i] = *(const float4*)(Bb + (size_t)(k0 + kr) * Ndim + nq * 4);
        }
    };
    auto stsA = [&](int buf) {
        uint32_t* base = As + buf * ASZ;
        #pragma unroll
        for (int i = 0; i < ALD; i++) {
            int lin = tid + i * 256;
            int row = lin >> 3;
            int kq  = lin & 7;
            uint4 v = make_uint4(f2tf32(pa[i].x), f2tf32(pa[i].y),
                                 f2tf32(pa[i].z), f2tf32(pa[i].w));
            *(uint4*)(base + row * ASR + kq * 4) = v;
        }
    };
    auto stsB = [&](int buf) {
        uint32_t* base = Bs + buf * BSZ;
        #pragma unroll
        for (int i = 0; i < BLD; i++) {
            int lin = tid + i * 256;
            int kr = lin / (BN / 4);
            int nq = lin % (BN / 4);
            uint4 v = make_uint4(f2tf32(pb[i].x), f2tf32(pb[i].y),
                                 f2tf32(pb[i].z), f2tf32(pb[i].w));
            *(uint4*)(base + kr * BSR + nq * 4) = v;
        }
    };

    const int arow = wm + (lane & 15);
    const int acol = (lane >> 4) * 4;
    const int bn0  = wn + (lane >> 2);
    const int bk0  = lane & 3;

    auto compute = [&](int buf) {
        uint32_t* Abs = As + buf * ASZ;
        uint32_t* Bbs = Bs + buf * BSZ;
        #pragma unroll
        for (int ks = 0; ks < 4; ks++) {
            uint32_t a[MT][4];
            #pragma unroll
            for (int i = 0; i < MT; i++) {
                uint32_t addr = smem_u32(Abs + (arow + i * 16) * ASR + ks * 8 + acol);
                ldsm_x4(a[i][0], a[i][1], a[i][2], a[i][3], addr);
            }
            uint32_t b0[NT], b1[NT];
            #pragma unroll
            for (int j = 0; j < NT; j++) {
                b0[j] = Bbs[(ks * 8 + bk0) * BSR + bn0 + j * 8];
                b1[j] = Bbs[(ks * 8 + 4 + bk0) * BSR + bn0 + j * 8];
            }
            #pragma unroll
            for (int i = 0; i < MT; i++)
                #pragma unroll
                for (int j = 0; j < NT; j++)
                    mma_tf32(c[i][j], a[i], b0[j], b1[j]);
        }
    };

    const int NKT = Kdim / BK;
    ldgA(0); ldgB(0);
    stsA(0); stsB(0);
    __syncthreads();
    for (int kt = 0; kt < NKT; kt++) {
        if (kt + 1 < NKT) { ldgA((kt + 1) * BK); ldgB((kt + 1) * BK); }
        compute(kt & 1);
        if (kt + 1 < NKT) { stsA((kt + 1) & 1); stsB((kt + 1) & 1); }
        __syncthreads();
    }

    float* Cb = C + (size_t)(by * BM + wm) * Ndim + (size_t)bx * BN + wn;
    const int r0 = lane >> 2;
    const int c0 = (lane & 3) * 2;
    #pragma unroll
    for (int i = 0; i < MT; i++)
        #pragma unroll
        for (int j = 0; j < NT; j++) {
            *(float2*)(Cb + (size_t)(i * 16 + r0) * Ndim + j * 8 + c0) =
                make_float2(c[i][j][0], c[i][j][1]);
            *(float2*)(Cb + (size_t)(i * 16 + r0 + 8) * Ndim + j * 8 + c0) =
                make_float2(c[i][j][2], c[i][j][3]);
        }
}

// ---------------- instance norm + lrelu ----------------
__global__ void inorm_kernel(const float* __restrict__ E, float* __restrict__ NF)
{
    int p = blockIdx.x, j = threadIdx.x;            // 256 threads
    __shared__ float sm[16];
    float v = E[(size_t)p*RD_ + j];

    float s1 = v;
    #pragma unroll
    for (int o=16;o>0;o>>=1) s1 += __shfl_xor_sync(0xffffffffu, s1, o);
    if ((j&31)==0) sm[j>>5] = s1;
    __syncthreads();
    if (j < 32) {
        float x = (j<8)? sm[j] : 0.f;
        #pragma unroll
        for (int o=4;o>0;o>>=1) x += __shfl_xor_sync(0xffffffffu, x, o);
        if (j==0) sm[8] = x;
    }
    __syncthreads();
    float mu = sm[8]*(1.f/RD_);
    float d  = v - mu;

    float s2 = d*d;
    #pragma unroll
    for (int o=16;o>0;o>>=1) s2 += __shfl_xor_sync(0xffffffffu, s2, o);
    if ((j&31)==0) sm[j>>5] = s2;
    __syncthreads();
    if (j < 32) {
        float x = (j<8)? sm[j] : 0.f;
        #pragma unroll
        for (int o=4;o>0;o>>=1) x += __shfl_xor_sync(0xffffffffu, x, o);
        if (j==0) sm[9] = x;
    }
    __syncthreads();
    float var = sm[9]*(1.f/RD_);
    float y = d * rsqrtf(var + EPS_);
    NF[(size_t)p*RD_ + j] = y>=0.f ? y : SLOPE_*y;
}

// ---------------- mesh glue -----------------------------------------------
// degrees + in-degree prefix scan, fused
__global__ void k_mesh_deg(const int* __restrict__ msrc,
                           const int* __restrict__ mdst)
{
    int b = blockIdx.x, t = threadIdx.x;            // 1024 threads
    __shared__ int co[M_], ci[M_], s[M_];
    co[t]=0; ci[t]=0;
    __syncthreads();
    const int* sp = msrc + b*ME_;
    const int* dp = mdst + b*ME_;
    for (int e=t;e<ME_;e+=M_) {
        atomicAdd(&co[sp[e]],1);
        atomicAdd(&ci[dp[e]],1);
    }
    __syncthreads();
    g_mouts[b*M_+t] = rsqrtf(fmaxf((float)co[t],1.f));
    g_mins [b*M_+t] = rsqrtf(fmaxf((float)ci[t],1.f));
    int orig = ci[t];
    s[t] = orig;
    __syncthreads();
    for (int o=1;o<M_;o<<=1) {
        int u = (t>=o)? s[t-o] : 0;
        __syncthreads();
        s[t] += u;
        __syncthreads();
    }
    int st = s[t] - orig;
    g_rowstart[b*M_+t] = st;
    g_cursor  [b*M_+t] = st;
}

__global__ void mbucket_kernel(const int* __restrict__ msrc,
                               const int* __restrict__ mdst,
                               const float* __restrict__ mew)
{
    int eg = blockIdx.x*256 + threadIdx.x;
    if (eg >= B_*ME_) return;
    int b = eg >> 14;
    int s = msrc[eg], d = mdst[eg];
    int pos = atomicAdd(&g_cursor[b*M_+d], 1);
    g_srcs[b*ME_+pos] = s;
    g_wgt [b*ME_+pos] = mew[eg] * g_mouts[b*M_+s];
}

template<int C>
__global__ void magg_k(const float* __restrict__ H, float* __restrict__ AGG)
{
    int node = blockIdx.x;                           // 0..4095
    int b = node >> 10;
    int n = node & (M_-1);
    int c = blockIdx.y*128 + threadIdx.x;
    int beg = g_rowstart[node];
    int end = (n==M_-1) ? ME_ : g_rowstart[node+1];
    const int*   sarr = g_srcs + b*ME_;
    const float* warr = g_wgt  + b*ME_;
    float acc = 0.f;
    for (int i=beg;i<end;i++)
        acc += H[(size_t)(b*M_ + sarr[i])*C + c] * warr[i];
    AGG[(size_t)node*C + c] = acc * g_mins[node];
}

template<bool WRITE>
__global__ void k_mesh_norm(const float* __restrict__ Hpre,
                            const float* __restrict__ gamma,
                            const float* __restrict__ beta,
                            const float* __restrict__ alpha,
                            float* __restrict__ Hn, int off)
{
    int b = blockIdx.x >> 2;
    int c = (blockIdx.x & 3)*128 + threadIdx.x;
    const float* A = Hpre + (size_t)b*M_*HM_;
    float s1 = 0.f, s2 = 0.f;
    #pragma unroll 4
    for (int r=0;r<M_;r++) { float v = A[(size_t)r*HM_+c]; s1+=v; s2+=v*v; }
    float mean = s1*(1.f/M_);
    float am = alpha[c]*mean;
    float var = s2*(1.f/M_) - 2.f*am*mean + am*am;
    float istd = rsqrtf(fmaxf(var,0.f) + EPS_);
    float g = gamma[c], bb = beta[c];
    float rs = 0.f;
    #pragma unroll 4
    for (int r=0;r<M_;r++) {
        float v = A[(size_t)r*HM_+c];
        float h = lrelu_f(g*(v-am)*istd + bb);
        if (WRITE) Hn[(size_t)(b*M_+r)*HM_ + c] = h;
        rs += h;
    }
    g_block[b*2*HM_ + off + c] = rs*(1.f/M_);
}

__global__ void final_kernel(const float* __restrict__ Wc, float* __restrict__ out)
{
    int t = threadIdx.x;                             // 256 threads
    float acc[OUT_];
    #pragma unroll
    for (int o=0;o<OUT_;o++) acc[o]=0.f;
    for (int i=t;i<B_*2*HM_;i+=256) {
        float v = lrelu_f(g_block[i]);
        #pragma unroll
        for (int o=0;o<OUT_;o++) acc[o] += v*Wc[(size_t)i*OUT_+o];
    }
    __shared__ float red[OUT_][256];
    #pragma unroll
    for (int o=0;o<OUT_;o++) red[o][t]=acc[o];
    __syncthreads();
    for (int s=128;s>0;s>>=1) {
        if (t<s) {
            #pragma unroll
            for (int o=0;o<OUT_;o++) red[o][t]+=red[o][t+s];
        }
        __syncthreads();
    }
    if (t<OUT_) out[t]=red[t][0];
}

// ---------------- launcher -------------------------------------------------
extern "C" void kernel_launch(void* const* d_in, const int* in_sizes, int n_in,
                              void* d_out, int out_size)
{
    (void)in_sizes; (void)n_in; (void)out_size;
    const float* feats = (const float*)d_in[0];
    const int*   psrc  = (const int*)  d_in[1];
    const int*   pdst  = (const int*)  d_in[2];
    const float* pew   = (const float*)d_in[3];
    const int*   msrc  = (const int*)  d_in[4];
    const int*   mdst  = (const int*)  d_in[5];
    const float* mew   = (const float*)d_in[6];
    const float* Wp1   = (const float*)d_in[7];
    const float* Wp2   = (const float*)d_in[8];
    const float* W_emb = (const float*)d_in[9];
    const float* gp1_g = (const float*)d_in[10];
    const float* gp1_b = (const float*)d_in[11];
    const float* gp1_a = (const float*)d_in[12];
    const float* gp2_g = (const float*)d_in[13];
    const float* gp2_b = (const float*)d_in[14];
    const float* gp2_a = (const float*)d_in[15];
    const float* gm1_g = (const float*)d_in[16];
    const float* gm1_b = (const float*)d_in[17];
    const float* gm1_a = (const float*)d_in[18];
    const float* gm2_g = (const float*)d_in[19];
    const float* gm2_b = (const float*)d_in[20];
    const float* gm2_a = (const float*)d_in[21];
    const float* Wm1   = (const float*)d_in[22];
    const float* Wm2   = (const float*)d_in[23];
    const float* Wc    = (const float*)d_in[24];
    float* out = (float*)d_out;

    float *pR,*pE,*pNF,*pNFa,*pHM,*pHMn,*pHMa,*pHM2;
    cudaGetSymbolAddress((void**)&pR,   g_R);
    cudaGetSymbolAddress((void**)&pE,   g_E);
    cudaGetSymbolAddress((void**)&pNF,  g_NF);
    cudaGetSymbolAddress((void**)&pNFa, g_NFa);
    cudaGetSymbolAddress((void**)&pHM,  g_HM);
    cudaGetSymbolAddress((void**)&pHMn, g_HMn);
    cudaGetSymbolAddress((void**)&pHMa, g_HMa);
    cudaGetSymbolAddress((void**)&pHM2, g_HM2);

    const int SM128 = (2*128*36 + 2*32*136) * 4;   // 71680 B
    cudaFuncSetAttribute(gemm_tf32<128,128>,
                         cudaFuncAttributeMaxDynamicSharedMemorySize, SM128);
    cudaFuncSetAttribute(k_patch_all,
                         cudaFuncAttributeMaxDynamicSharedMemorySize, SMB_PATCH);

    // ---- patch phase: single fused kernel ----
    k_patch_all<<<P_/2, 256, SMB_PATCH>>>(
        feats, psrc, pdst, pew, Wp1, Wp2,
        gp1_g, gp1_b, gp1_a, gp2_g, gp2_b, gp2_a);

    // ---- embed + instance norm ----
    gemm_tf32<128,128><<<(P_/128)*(RD_/128), 256, SM128>>>(
        pR, W_emb, pE, P_, RD_, RTOT_);
    inorm_kernel<<<P_, RD_>>>(pE, pNF);

    // ---- mesh CSR build ----
    k_mesh_deg<<<B_, M_>>>(msrc, mdst);
    mbucket_kernel<<<B_*ME_/256, 256>>>(msrc, mdst, mew);

    // ---- mesh layer 1 (pre-aggregate in 256-dim) ----
    magg_k<RD_><<<dim3(B_*M_, RD_/128), 128>>>(pNF, pNFa);
    gemm_tf32<128,128><<<(B_*M_/128)*(HM_/128), 256, SM128>>>(
        pNFa, Wm1, pHM, B_*M_, HM_, RD_);
    k_mesh_norm<true><<<B_*4, 128>>>(pHM, gm1_g, gm1_b, gm1_a, pHMn, 0);

    // ---- mesh layer 2 ----
    magg_k<HM_><<<dim3(B_*M_, HM_/128), 128>>>(pHMn, pHMa);
    gemm_tf32<128,128><<<(B_*M_/128)*(HM_/128), 256, SM128>>>(
        pHMa, Wm2, pHM2, B_*M_, HM_, HM_);
    k_mesh_norm<false><<<B_*4, 128>>>(pHM2, gm2_g, gm2_b, gm2_a, nullptr, HM_);

    // ---- classifier ----
    final_kernel<<<1, 256>>>(Wc, out);
}

// round 5
// speedup vs baseline: 4.2297x; 1.9085x over previous
#include <cuda_runtime.h>
#include <cstdint>

#define P_ 4096
#define PN_ 32
#define PE_ 128
#define B_ 4
#define M_ 1024
#define ME_ 16384
#define IN_ 64
#define HP_ 256
#define HP4_ 64
#define RD_ 256
#define HM_ 512
#define OUT_ 16
#define RTOT_ (IN_+HP_+HP4_)   // 384
#define EPS_ 1e-5f
#define SLOPE_ 0.01f

// ---------------- scratch ----------------
__device__ float g_R  [(size_t)P_*RTOT_];      // readout concat  [4096,384]
__device__ float g_E  [(size_t)P_*RD_];        // patch embed     [4096,256]
__device__ float g_NF [(size_t)P_*RD_];        // node feats      [4096,256]
__device__ float g_NFa[(size_t)B_*M_*RD_];     // mesh-agg node feats
__device__ float g_HM [(size_t)B_*M_*HM_];     // mesh conv1 pre-norm
__device__ float g_HMn[(size_t)B_*M_*HM_];     // mesh h1 activated
__device__ float g_HMa[(size_t)B_*M_*HM_];     // mesh-agg h1
__device__ float g_HM2[(size_t)B_*M_*HM_];     // mesh conv2 pre-norm
__device__ float g_mouts[B_*M_], g_mins[B_*M_];
__device__ int   g_rowstart[B_*M_], g_cursor[B_*M_];
__device__ int   g_srcs[B_*ME_];
__device__ float g_wgt [B_*ME_];
// zero-initialized accumulator pool (cleared by k_zero each run):
//  [0,4096)      co (int)        [4096,8192)   ci (int)
//  [8192,10240)  s1 layer1       [10240,12288) s2 layer1
//  [12288,14336) s1 layer2       [14336,16384) s2 layer2
//  [16384,20480) block readout
#define POOL_W 20480
__device__ uint32_t g_pool[POOL_W];

// ---------------- tf32 helpers ----------------
__device__ __forceinline__ uint32_t f2tf32(float f) {
    uint32_t u;
    asm("cvt.rna.tf32.f32 %0, %1;" : "=r"(u) : "f"(f));
    return u;
}
__device__ __forceinline__ uint32_t smem_u32(const void* p) {
    return static_cast<uint32_t>(__cvta_generic_to_shared(p));
}
__device__ __forceinline__ void ldsm_x4(uint32_t& r0, uint32_t& r1,
                                        uint32_t& r2, uint32_t& r3, uint32_t addr) {
    asm volatile("ldmatrix.sync.aligned.m8n8.x4.shared.b16 {%0,%1,%2,%3}, [%4];\n"
                 : "=r"(r0), "=r"(r1), "=r"(r2), "=r"(r3) : "r"(addr));
}
__device__ __forceinline__ void mma_tf32(float* c, const uint32_t* a,
                                         uint32_t b0, uint32_t b1) {
    asm volatile(
        "mma.sync.aligned.m16n8k8.row.col.f32.tf32.tf32.f32 "
        "{%0,%1,%2,%3}, {%4,%5,%6,%7}, {%8,%9}, {%0,%1,%2,%3};\n"
        : "+f"(c[0]), "+f"(c[1]), "+f"(c[2]), "+f"(c[3])
        : "r"(a[0]), "r"(a[1]), "r"(a[2]), "r"(a[3]), "r"(b0), "r"(b1));
}
__device__ __forceinline__ float red8(float v) {
    v += __shfl_xor_sync(0xffffffffu, v, 4);
    v += __shfl_xor_sync(0xffffffffu, v, 8);
    v += __shfl_xor_sync(0xffffffffu, v, 16);
    return v;
}
__device__ __forceinline__ float lrelu_f(float x) { return x >= 0.f ? x : SLOPE_*x; }

__global__ void k_zero()
{
    int i = blockIdx.x*1024 + threadIdx.x;
    if (i < POOL_W) g_pool[i] = 0u;
}

// ============== fused patch phase: one CTA = 2 patches =====================
#define SMW_TOTAL 28416
#define SMB_PATCH (SMW_TOTAL*4)

__global__ void __launch_bounds__(256)
k_patch_all(const float* __restrict__ feats, const int* __restrict__ src,
            const int* __restrict__ dst, const float* __restrict__ ew,
            const float* __restrict__ Wp1, const float* __restrict__ Wp2,
            const float* __restrict__ g1g, const float* __restrict__ g1b,
            const float* __restrict__ g1a, const float* __restrict__ g2g,
            const float* __restrict__ g2b, const float* __restrict__ g2a)
{
    extern __shared__ uint32_t S[];
    float*    Wsh  = (float*)S;                  // 2048
    float*    outs = (float*)(S + 2048);         // 64
    float*    ins  = (float*)(S + 2112);         // 64
    int*      cnt  = (int*)  (S + 2176);         // 128
    float*    Xs   = (float*)(S + 2304);         // [64][68]
    uint32_t* A1   = S + 2304 + 4352;            // [64][68]
    uint32_t* Bs2  = S + 2304;                   // [128][72]
    uint32_t* B1   = S + 11520;                  // [64][264]
    uint32_t* As2  = S + 11520;                  // [64][260]
    float*    H2s  = (float*)(S + 11520);        // [64][68]

    const int t    = threadIdx.x;
    const int blk  = blockIdx.x;
    const int lane = t & 31;
    const int wid  = t >> 5;

    // ---- phase 0: zero W/cnt, load X, load Wp1 ----
    #pragma unroll
    for (int i = 0; i < 8; i++) Wsh[t + 256*i] = 0.f;
    if (t < 128) cnt[t] = 0;
    {
        const float4* f4 = (const float4*)(feats + (size_t)blk*64*IN_);
        #pragma unroll
        for (int i = 0; i < 4; i++) {
            int lin = t + i*256;
            int lr = lin >> 4, cq = lin & 15;
            *(float4*)(Xs + lr*68 + cq*4) = f4[lin];
        }
        const float4* w4 = (const float4*)Wp1;
        #pragma unroll
        for (int i = 0; i < 16; i++) {
            int lin = t + i*256;
            int k = lin >> 6, nq = lin & 63;
            float4 v = w4[lin];
            *(uint4*)(B1 + k*264 + nq*4) =
                make_uint4(f2tf32(v.x), f2tf32(v.y), f2tf32(v.z), f2tf32(v.w));
        }
    }
    __syncthreads();

    // ---- phase 1: build dense normalized adjacency for 2 patches ----
    {
        int q = t >> 7, e = t & 127;
        int p = blk*2 + q;
        int s = src[p*PE_ + e], d = dst[p*PE_ + e];
        atomicAdd(&Wsh[q*1024 + d*PN_ + s], ew[p*PE_ + e]);
        atomicAdd(&cnt[q*PN_ + s], 1);
        atomicAdd(&cnt[64 + q*PN_ + d], 1);
    }
    __syncthreads();
    if (t < 64) {
        outs[t] = rsqrtf(fmaxf((float)cnt[t], 1.f));
        ins[t]  = rsqrtf(fmaxf((float)cnt[64 + t], 1.f));
    }
    __syncthreads();
    #pragma unroll
    for (int i = 0; i < 8; i++) {
        int idx = t + 256*i;
        int q = idx >> 10, rem = idx & 1023;
        int dn = rem >> 5, sn = rem & 31;
        Wsh[idx] *= ins[q*PN_ + dn] * outs[q*PN_ + sn];
    }
    __syncthreads();

    // ---- phase 2: Xa = W @ X (into A1 as tf32), r0 readout ----
    {
        int col = t & 63, dg = t >> 6;
        #pragma unroll
        for (int q = 0; q < 2; q++) {
            float x[PN_];
            #pragma unroll
            for (int s = 0; s < PN_; s++) x[s] = Xs[(q*32 + s)*68 + col];
            if (dg == 0) {
                float s1 = 0.f;
                #pragma unroll
                for (int s = 0; s < PN_; s++) s1 += x[s];
                g_R[(size_t)(blk*2 + q)*RTOT_ + col] = s1 * (1.f/PN_);
            }
            #pragma unroll
            for (int dd = 0; dd < 8; dd++) {
                int d = dg*8 + dd;
                const float* wrow = &Wsh[q*1024 + d*PN_];
                float acc = 0.f;
                #pragma unroll
                for (int s = 0; s < PN_; s++) acc += wrow[s] * x[s];
                A1[(q*32 + d)*68 + col] = f2tf32(acc);
            }
        }
    }
    __syncthreads();

    // ---- phase 3: conv1 mma: [64,64] @ [64,256] ----
    const int wm  = (wid >> 2) * 32;
    const int wn  = (wid & 3) * 64;
    const int arow = wm + (lane & 15);
    const int acol = (lane >> 4) * 4;
    const int bn0  = wn + (lane >> 2);
    const int bk0  = lane & 3;

    float c1[2][8][4];
    #pragma unroll
    for (int i = 0; i < 2; i++)
        #pragma unroll
        for (int j = 0; j < 8; j++)
            #pragma unroll
            for (int q = 0; q < 4; q++) c1[i][j][q] = 0.f;

    #pragma unroll
    for (int ks = 0; ks < 8; ks++) {
        uint32_t a[2][4];
        #pragma unroll
        for (int i = 0; i < 2; i++) {
            uint32_t addr = smem_u32(A1 + (arow + i*16)*68 + ks*8 + acol);
            ldsm_x4(a[i][0], a[i][1], a[i][2], a[i][3], addr);
        }
        uint32_t b0[8], b1v[8];
        #pragma unroll
        for (int j = 0; j < 8; j++) {
            b0[j]  = B1[(ks*8 + bk0)*264 + bn0 + j*8];
            b1v[j] = B1[(ks*8 + 4 + bk0)*264 + bn0 + j*8];
        }
        #pragma unroll
        for (int i = 0; i < 2; i++)
            #pragma unroll
            for (int j = 0; j < 8; j++)
                mma_tf32(c1[i][j], a[i], b0[j], b1v[j]);
    }
    __syncthreads();

    // ---- phase 4: GraphNorm + lrelu + r1; H1 -> As2 (tf32) ----
    {
        const int pat = blk*2 + (wid >> 2);
        const int r0 = lane >> 2;
        const int c0 = (lane & 3) * 2;
        const float inv32 = 1.f / 32.f;
        #pragma unroll
        for (int j = 0; j < 8; j++) {
            int ca = wn + j*8 + c0;
            float va0=c1[0][j][0], va1=c1[0][j][2], va2=c1[1][j][0], va3=c1[1][j][2];
            float vb0=c1[0][j][1], vb1=c1[0][j][3], vb2=c1[1][j][1], vb3=c1[1][j][3];
            float ma = red8(va0+va1+va2+va3) * inv32;
            float mb = red8(vb0+vb1+vb2+vb3) * inv32;
            float ama = __ldg(&g1a[ca])   * ma;
            float amb = __ldg(&g1a[ca+1]) * mb;
            float da0=va0-ama, da1=va1-ama, da2=va2-ama, da3=va3-ama;
            float db0=vb0-amb, db1=vb1-amb, db2=vb2-amb, db3=vb3-amb;
            float qa = red8(da0*da0+da1*da1+da2*da2+da3*da3);
            float qb = red8(db0*db0+db1*db1+db2*db2+db3*db3);
            float ia = rsqrtf(qa*inv32 + EPS_);
            float ib = rsqrtf(qb*inv32 + EPS_);
            float ga = __ldg(&g1g[ca]),   ba = __ldg(&g1b[ca]);
            float gb = __ldg(&g1g[ca+1]), bb = __ldg(&g1b[ca+1]);
            float ha0=lrelu_f(ga*da0*ia+ba), ha1=lrelu_f(ga*da1*ia+ba);
            float ha2=lrelu_f(ga*da2*ia+ba), ha3=lrelu_f(ga*da3*ia+ba);
            float hb0=lrelu_f(gb*db0*ib+bb), hb1=lrelu_f(gb*db1*ib+bb);
            float hb2=lrelu_f(gb*db2*ib+bb), hb3=lrelu_f(gb*db3*ib+bb);
            uint32_t* dst0 = As2 + (wm + r0)*260 + wn + j*8 + c0;
            *(uint2*)(dst0)            = make_uint2(f2tf32(ha0), f2tf32(hb0));
            *(uint2*)(dst0 + 8*260)    = make_uint2(f2tf32(ha1), f2tf32(hb1));
            *(uint2*)(dst0 + 16*260)   = make_uint2(f2tf32(ha2), f2tf32(hb2));
            *(uint2*)(dst0 + 24*260)   = make_uint2(f2tf32(ha3), f2tf32(hb3));
            float ra = red8(ha0+ha1+ha2+ha3) * inv32;
            float rb = red8(hb0+hb1+hb2+hb3) * inv32;
            if (r0 == 0) {
                g_R[(size_t)pat*RTOT_ + IN_ + ca]     = ra;
                g_R[(size_t)pat*RTOT_ + IN_ + ca + 1] = rb;
            }
        }
    }
    __syncthreads();

    // ---- phase 5: conv2 mma: [64,256] @ [256,64], K in 2 chunks of 128 ----
    const int wn2  = (wid & 3) * 16;
    const int bn02 = wn2 + (lane >> 2);
    float c2[2][2][4];
    #pragma unroll
    for (int i = 0; i < 2; i++)
        #pragma unroll
        for (int j = 0; j < 2; j++)
            #pragma unroll
            for (int q = 0; q < 4; q++) c2[i][j][q] = 0.f;

    #pragma unroll
    for (int ch = 0; ch < 2; ch++) {
        const float4* w4 = (const float4*)(Wp2 + (size_t)ch*128*HP4_);
        #pragma unroll
        for (int i = 0; i < 8; i++) {
            int lin = t + i*256;
            int k = lin >> 4, nq = lin & 15;
            float4 v = w4[lin];
            *(uint4*)(Bs2 + k*72 + nq*4) =
                make_uint4(f2tf32(v.x), f2tf32(v.y), f2tf32(v.z), f2tf32(v.w));
        }
        __syncthreads();
        #pragma unroll
        for (int ks = 0; ks < 16; ks++) {
            uint32_t a[2][4];
            #pragma unroll
            for (int i = 0; i < 2; i++) {
                uint32_t addr = smem_u32(As2 + (arow + i*16)*260 + ch*128 + ks*8 + acol);
                ldsm_x4(a[i][0], a[i][1], a[i][2], a[i][3], addr);
            }
            uint32_t b0[2], b1v[2];
            #pragma unroll
            for (int j = 0; j < 2; j++) {
                b0[j]  = Bs2[(ks*8 + bk0)*72 + bn02 + j*8];
                b1v[j] = Bs2[(ks*8 + 4 + bk0)*72 + bn02 + j*8];
            }
            #pragma unroll
            for (int i = 0; i < 2; i++)
                #pragma unroll
                for (int j = 0; j < 2; j++)
                    mma_tf32(c2[i][j], a[i], b0[j], b1v[j]);
        }
        __syncthreads();
    }

    // ---- phase 6: H2 -> smem ----
    {
        const int r0 = lane >> 2;
        const int c0 = (lane & 3) * 2;
        #pragma unroll
        for (int i = 0; i < 2; i++)
            #pragma unroll
            for (int j = 0; j < 2; j++) {
                float* d0 = H2s + (wm + i*16 + r0)*68 + wn2 + j*8 + c0;
                *(float2*)(d0)        = make_float2(c2[i][j][0], c2[i][j][1]);
                *(float2*)(d0 + 8*68) = make_float2(c2[i][j][2], c2[i][j][3]);
            }
    }
    __syncthreads();

    // ---- phase 7: agg(W) + GraphNorm + lrelu + r2 readout ----
    if (t < 128) {
        int q = t >> 6, col = t & 63;
        float h[PN_];
        #pragma unroll
        for (int s = 0; s < PN_; s++) h[s] = H2s[(q*32 + s)*68 + col];
        float xv[PN_];
        #pragma unroll
        for (int d = 0; d < PN_; d++) {
            const float* wrow = &Wsh[q*1024 + d*PN_];
            float acc = 0.f;
            #pragma unroll
            for (int s = 0; s < PN_; s++) acc += wrow[s] * h[s];
            xv[d] = acc;
        }
        float s1 = 0.f;
        #pragma unroll
        for (int d = 0; d < PN_; d++) s1 += xv[d];
        float am = __ldg(&g2a[col]) * s1 * (1.f/PN_);
        float s2 = 0.f;
        #pragma unroll
        for (int d = 0; d < PN_; d++) { float u = xv[d]-am; s2 += u*u; }
        float istd = rsqrtf(s2*(1.f/PN_) + EPS_);
        float g = __ldg(&g2g[col]), bb = __ldg(&g2b[col]);
        float rs = 0.f;
        #pragma unroll
        for (int d = 0; d < PN_; d++) rs += lrelu_f(g*(xv[d]-am)*istd + bb);
        g_R[(size_t)(blk*2 + q)*RTOT_ + IN_ + HP_ + col] = rs*(1.f/PN_);
    }
}

// ---------------- tf32 GEMM; optional column-stats epilogue ----------------
template<int BM, int BN, bool STATS>
__global__ void __launch_bounds__(256)
gemm_tf32(const float* __restrict__ A, const float* __restrict__ B,
          float* __restrict__ C, int Mdim, int Ndim, int Kdim,
          float* __restrict__ s1p, float* __restrict__ s2p)
{
    constexpr int BK  = 32;
    constexpr int WM  = 32;
    constexpr int WN  = BN / 2;
    constexpr int MT  = WM / 16;
    constexpr int NT  = WN / 8;
    constexpr int ASR = BK + 4;
    constexpr int BSR = BN + 8;
    constexpr int ASZ = BM * ASR;
    constexpr int BSZ = BK * BSR;
    constexpr int ALD = BM * BK / 4 / 256;
    constexpr int BLD = BK * BN / 4 / 256;

    extern __shared__ uint32_t sm_[];
    uint32_t* As = sm_;
    uint32_t* Bs = sm_ + 2 * ASZ;

    const int tid  = threadIdx.x;
    const int lane = tid & 31;
    const int wid  = tid >> 5;
    const int nblk = Ndim / BN;
    const int bx = blockIdx.x % nblk;
    const int by = blockIdx.x / nblk;
    const float* Ab = A + (size_t)by * BM * Kdim;
    const float* Bb = B + (size_t)bx * BN;

    const int wm = (wid >> 1) * WM;
    const int wn = (wid & 1) * WN;

    float c[MT][NT][4];
    #pragma unroll
    for (int i = 0; i < MT; i++)
        #pragma unroll
        for (int j = 0; j < NT; j++)
            #pragma unroll
            for (int q = 0; q < 4; q++) c[i][j][q] = 0.f;

    float4 pa[ALD], pb[BLD];

    auto ldgA = [&](int k0) {
        #pragma unroll
        for (int i = 0; i < ALD; i++) {
            int lin = tid + i * 256;
            int row = lin >> 3;
            int kq  = lin & 7;
            pa[i] = *(const float4*)(Ab + (size_t)row * Kdim + k0 + kq * 4);
        }
    };
    auto ldgB = [&](int k0) {
        #pragma unroll
        for (int i = 0; i < BLD; i++) {
            int lin = tid + i * 256;
            int kr = lin / (BN / 4);
            int nq = lin % (BN / 4);
            pb[i] = *(const float4*)(Bb + (size_t)(k0 + kr) * Ndim + nq * 4);
        }
    };
    auto stsA = [&](int buf) {
        uint32_t* base = As + buf * ASZ;
        #pragma unroll
        for (int i = 0; i < ALD; i++) {
            int lin = tid + i * 256;
            int row = lin >> 3;
            int kq  = lin & 7;
            uint4 v = make_uint4(f2tf32(pa[i].x), f2tf32(pa[i].y),
                                 f2tf32(pa[i].z), f2tf32(pa[i].w));
            *(uint4*)(base + row * ASR + kq * 4) = v;
        }
    };
    auto stsB = [&](int buf) {
        uint32_t* base = Bs + buf * BSZ;
        #pragma unroll
        for (int i = 0; i < BLD; i++) {
            int lin = tid + i * 256;
            int kr = lin / (BN / 4);
            int nq = lin % (BN / 4);
            uint4 v = make_uint4(f2tf32(pb[i].x), f2tf32(pb[i].y),
                                 f2tf32(pb[i].z), f2tf32(pb[i].w));
            *(uint4*)(base + kr * BSR + nq * 4) = v;
        }
    };

    const int arow = wm + (lane & 15);
    const int acol = (lane >> 4) * 4;
    const int bn0  = wn + (lane >> 2);
    const int bk0  = lane & 3;

    auto compute = [&](int buf) {
        uint32_t* Abs = As + buf * ASZ;
        uint32_t* Bbs = Bs + buf * BSZ;
        #pragma unroll
        for (int ks = 0; ks < 4; ks++) {
            uint32_t a[MT][4];
            #pragma unroll
            for (int i = 0; i < MT; i++) {
                uint32_t addr = smem_u32(Abs + (arow + i * 16) * ASR + ks * 8 + acol);
                ldsm_x4(a[i][0], a[i][1], a[i][2], a[i][3], addr);
            }
            uint32_t b0[NT], b1[NT];
            #pragma unroll
            for (int j = 0; j < NT; j++) {
                b0[j] = Bbs[(ks * 8 + bk0) * BSR + bn0 + j * 8];
                b1[j] = Bbs[(ks * 8 + 4 + bk0) * BSR + bn0 + j * 8];
            }
            #pragma unroll
            for (int i = 0; i < MT; i++)
                #pragma unroll
                for (int j = 0; j < NT; j++)
                    mma_tf32(c[i][j], a[i], b0[j], b1[j]);
        }
    };

    const int NKT = Kdim / BK;
    ldgA(0); ldgB(0);
    stsA(0); stsB(0);
    __syncthreads();
    for (int kt = 0; kt < NKT; kt++) {
        if (kt + 1 < NKT) { ldgA((kt + 1) * BK); ldgB((kt + 1) * BK); }
        compute(kt & 1);
        if (kt + 1 < NKT) { stsA((kt + 1) & 1); stsB((kt + 1) & 1); }
        __syncthreads();
    }

    float* Cb = C + (size_t)(by * BM + wm) * Ndim + (size_t)bx * BN + wn;
    const int r0 = lane >> 2;
    const int c0 = (lane & 3) * 2;
    #pragma unroll
    for (int i = 0; i < MT; i++)
        #pragma unroll
        for (int j = 0; j < NT; j++) {
            *(float2*)(Cb + (size_t)(i * 16 + r0) * Ndim + j * 8 + c0) =
                make_float2(c[i][j][0], c[i][j][1]);
            *(float2*)(Cb + (size_t)(i * 16 + r0 + 8) * Ndim + j * 8 + c0) =
                make_float2(c[i][j][2], c[i][j][3]);
        }

    if constexpr (STATS) {
        // per-column sum / sum-of-squares over this warp's 32 rows
        // (BM=128 rows all lie within one mesh graph since 1024 % 128 == 0)
        const int b = (by * BM) / M_;
        #pragma unroll
        for (int j = 0; j < NT; j++) {
            int gcol = bx * BN + wn + j * 8 + c0;
            float va0=c[0][j][0], va1=c[0][j][2], va2=c[1][j][0], va3=c[1][j][2];
            float vb0=c[0][j][1], vb1=c[0][j][3], vb2=c[1][j][1], vb3=c[1][j][3];
            float sa = red8(va0+va1+va2+va3);
            float sb = red8(vb0+vb1+vb2+vb3);
            float qa = red8(va0*va0+va1*va1+va2*va2+va3*va3);
            float qb = red8(vb0*vb0+vb1*vb1+vb2*vb2+vb3*vb3);
            if (r0 == 0) {
                atomicAdd(&s1p[b*HM_ + gcol],     sa);
                atomicAdd(&s1p[b*HM_ + gcol + 1], sb);
                atomicAdd(&s2p[b*HM_ + gcol],     qa);
                atomicAdd(&s2p[b*HM_ + gcol + 1], qb);
            }
        }
    }
}

// ---------------- instance norm + lrelu ----------------
__global__ void inorm_kernel(const float* __restrict__ E, float* __restrict__ NF)
{
    int p = blockIdx.x, j = threadIdx.x;            // 256 threads
    __shared__ float sm[16];
    float v = E[(size_t)p*RD_ + j];

    float s1 = v;
    #pragma unroll
    for (int o=16;o>0;o>>=1) s1 += __shfl_xor_sync(0xffffffffu, s1, o);
    if ((j&31)==0) sm[j>>5] = s1;
    __syncthreads();
    if (j < 32) {
        float x = (j<8)? sm[j] : 0.f;
        #pragma unroll
        for (int o=4;o>0;o>>=1) x += __shfl_xor_sync(0xffffffffu, x, o);
        if (j==0) sm[8] = x;
    }
    __syncthreads();
    float mu = sm[8]*(1.f/RD_);
    float d  = v - mu;

    float s2 = d*d;
    #pragma unroll
    for (int o=16;o>0;o>>=1) s2 += __shfl_xor_sync(0xffffffffu, s2, o);
    if ((j&31)==0) sm[j>>5] = s2;
    __syncthreads();
    if (j < 32) {
        float x = (j<8)? sm[j] : 0.f;
        #pragma unroll
        for (int o=4;o>0;o>>=1) x += __shfl_xor_sync(0xffffffffu, x, o);
        if (j==0) sm[9] = x;
    }
    __syncthreads();
    float var = sm[9]*(1.f/RD_);
    float y = d * rsqrtf(var + EPS_);
    NF[(size_t)p*RD_ + j] = y>=0.f ? y : SLOPE_*y;
}

// ---------------- mesh glue -----------------------------------------------
__global__ void k_mdeg(const int* __restrict__ msrc, const int* __restrict__ mdst)
{
    int eg = blockIdx.x*256 + threadIdx.x;
    if (eg >= B_*ME_) return;
    int b = eg >> 14;
    int* co = (int*)g_pool;
    int* ci = (int*)g_pool + B_*M_;
    atomicAdd(&co[b*M_ + msrc[eg]], 1);
    atomicAdd(&ci[b*M_ + mdst[eg]], 1);
}

__global__ void k_mscan()
{
    int b = blockIdx.x, t = threadIdx.x;            // 1024 threads
    __shared__ int s[M_];
    const int* co = (const int*)g_pool;
    const int* ci = (const int*)g_pool + B_*M_;
    g_mouts[b*M_+t] = rsqrtf(fmaxf((float)co[b*M_+t],1.f));
    g_mins [b*M_+t] = rsqrtf(fmaxf((float)ci[b*M_+t],1.f));
    int orig = ci[b*M_+t];
    s[t] = orig;
    __syncthreads();
    for (int o=1;o<M_;o<<=1) {
        int u = (t>=o)? s[t-o] : 0;
        __syncthreads();
        s[t] += u;
        __syncthreads();
    }
    int st = s[t] - orig;
    g_rowstart[b*M_+t] = st;
    g_cursor  [b*M_+t] = st;
}

__global__ void mbucket_kernel(const int* __restrict__ msrc,
                               const int* __restrict__ mdst,
                               const float* __restrict__ mew)
{
    int eg = blockIdx.x*256 + threadIdx.x;
    if (eg >= B_*ME_) return;
    int b = eg >> 14;
    int s = msrc[eg], d = mdst[eg];
    int pos = atomicAdd(&g_cursor[b*M_+d], 1);
    g_srcs[b*ME_+pos] = s;
    g_wgt [b*ME_+pos] = mew[eg] * g_mouts[b*M_+s];
}

template<int C>
__global__ void magg_k(const float* __restrict__ H, float* __restrict__ AGG)
{
    int node = blockIdx.x;                           // 0..4095
    int b = node >> 10;
    int n = node & (M_-1);
    int c = blockIdx.y*128 + threadIdx.x;
    int beg = g_rowstart[node];
    int end = (n==M_-1) ? ME_ : g_rowstart[node+1];
    const int*   sarr = g_srcs + b*ME_;
    const float* warr = g_wgt  + b*ME_;
    float acc = 0.f;
    for (int i=beg;i<end;i++)
        acc += H[(size_t)(b*M_ + sarr[i])*C + c] * warr[i];
    AGG[(size_t)node*C + c] = acc * g_mins[node];
}

// normalize + lrelu + readout-accumulate; grid (HM/128, 4096/64), 128 thr
template<bool WRITE>
__global__ void k_mapply(const float* __restrict__ Hpre,
                         const float* __restrict__ s1p, const float* __restrict__ s2p,
                         const float* __restrict__ gamma,
                         const float* __restrict__ beta,
                         const float* __restrict__ alpha,
                         float* __restrict__ Hn, int off)
{
    int c = blockIdx.x*128 + threadIdx.x;            // 0..511
    int rbase = blockIdx.y*64;                       // 64-row chunk
    int b = rbase >> 10;
    float* block = (float*)g_pool + 4*B_*M_ /*co+ci as words? careful*/;
    // pool words: co(4096 int) + ci(4096 int) + s1a(2048)+s2a(2048)+s1b(2048)+s2b(2048)
    block = (float*)g_pool + (2*B_*M_ + 4*B_*HM_);

    float S1 = s1p[b*HM_ + c];
    float S2 = s2p[b*HM_ + c];
    float mean = S1 * (1.f/M_);
    float am   = alpha[c] * mean;
    float var  = S2*(1.f/M_) - 2.f*am*mean + am*am;
    float istd = rsqrtf(fmaxf(var, 0.f) + EPS_);
    float g = gamma[c], bb = beta[c];

    float acc = 0.f;
    const float* Hp = Hpre + (size_t)rbase*HM_ + c;
    float* Ho = WRITE ? (Hn + (size_t)rbase*HM_ + c) : nullptr;
    #pragma unroll 4
    for (int r = 0; r < 64; r++) {
        float v = Hp[(size_t)r*HM_];
        float h = lrelu_f(g*(v-am)*istd + bb);
        if (WRITE) Ho[(size_t)r*HM_] = h;
        acc += h;
    }
    atomicAdd(&block[b*2*HM_ + off + c], acc);
}

__global__ void final_kernel(const float* __restrict__ Wc, float* __restrict__ out)
{
    int t = threadIdx.x;                             // 256 threads
    const float* block = (const float*)g_pool + (2*B_*M_ + 4*B_*HM_);
    float acc[OUT_];
    #pragma unroll
    for (int o=0;o<OUT_;o++) acc[o]=0.f;
    for (int i=t;i<B_*2*HM_;i+=256) {
        float v = lrelu_f(block[i] * (1.f/M_));
        #pragma unroll
        for (int o=0;o<OUT_;o++) acc[o] += v*Wc[(size_t)i*OUT_+o];
    }
    __shared__ float red[OUT_][256];
    #pragma unroll
    for (int o=0;o<OUT_;o++) red[o][t]=acc[o];
    __syncthreads();
    for (int s=128;s>0;s>>=1) {
        if (t<s) {
            #pragma unroll
            for (int o=0;o<OUT_;o++) red[o][t]+=red[o][t+s];
        }
        __syncthreads();
    }
    if (t<OUT_) out[t]=red[t][0];
}

// ---------------- launcher -------------------------------------------------
extern "C" void kernel_launch(void* const* d_in, const int* in_sizes, int n_in,
                              void* d_out, int out_size)
{
    (void)in_sizes; (void)n_in; (void)out_size;
    const float* feats = (const float*)d_in[0];
    const int*   psrc  = (const int*)  d_in[1];
    const int*   pdst  = (const int*)  d_in[2];
    const float* pew   = (const float*)d_in[3];
    const int*   msrc  = (const int*)  d_in[4];
    const int*   mdst  = (const int*)  d_in[5];
    const float* mew   = (const float*)d_in[6];
    const float* Wp1   = (const float*)d_in[7];
    const float* Wp2   = (const float*)d_in[8];
    const float* W_emb = (const float*)d_in[9];
    const float* gp1_g = (const float*)d_in[10];
    const float* gp1_b = (const float*)d_in[11];
    const float* gp1_a = (const float*)d_in[12];
    const float* gp2_g = (const float*)d_in[13];
    const float* gp2_b = (const float*)d_in[14];
    const float* gp2_a = (const float*)d_in[15];
    const float* gm1_g = (const float*)d_in[16];
    const float* gm1_b = (const float*)d_in[17];
    const float* gm1_a = (const float*)d_in[18];
    const float* gm2_g = (const float*)d_in[19];
    const float* gm2_b = (const float*)d_in[20];
    const float* gm2_a = (const float*)d_in[21];
    const float* Wm1   = (const float*)d_in[22];
    const float* Wm2   = (const float*)d_in[23];
    const float* Wc    = (const float*)d_in[24];
    float* out = (float*)d_out;

    float *pR,*pE,*pNF,*pNFa,*pHM,*pHMn,*pHMa,*pHM2;
    uint32_t* pPool;
    cudaGetSymbolAddress((void**)&pR,   g_R);
    cudaGetSymbolAddress((void**)&pE,   g_E);
    cudaGetSymbolAddress((void**)&pNF,  g_NF);
    cudaGetSymbolAddress((void**)&pNFa, g_NFa);
    cudaGetSymbolAddress((void**)&pHM,  g_HM);
    cudaGetSymbolAddress((void**)&pHMn, g_HMn);
    cudaGetSymbolAddress((void**)&pHMa, g_HMa);
    cudaGetSymbolAddress((void**)&pHM2, g_HM2);
    cudaGetSymbolAddress((void**)&pPool, g_pool);
    float* pS1a = (float*)pPool + 2*B_*M_;
    float* pS2a = pS1a + B_*HM_;
    float* pS1b = pS2a + B_*HM_;
    float* pS2b = pS1b + B_*HM_;

    const int SM128 = (2*128*36 + 2*32*136) * 4;   // 71680 B
    cudaFuncSetAttribute(gemm_tf32<128,128,false>,
                         cudaFuncAttributeMaxDynamicSharedMemorySize, SM128);
    cudaFuncSetAttribute(gemm_tf32<128,128,true>,
                         cudaFuncAttributeMaxDynamicSharedMemorySize, SM128);
    cudaFuncSetAttribute(k_patch_all,
                         cudaFuncAttributeMaxDynamicSharedMemorySize, SMB_PATCH);

    // ---- clear accumulator pool ----
    k_zero<<<(POOL_W+1023)/1024, 1024>>>();

    // ---- patch phase: single fused kernel ----
    k_patch_all<<<P_/2, 256, SMB_PATCH>>>(
        feats, psrc, pdst, pew, Wp1, Wp2,
        gp1_g, gp1_b, gp1_a, gp2_g, gp2_b, gp2_a);

    // ---- embed + instance norm ----
    gemm_tf32<128,128,false><<<(P_/128)*(RD_/128), 256, SM128>>>(
        pR, W_emb, pE, P_, RD_, RTOT_, nullptr, nullptr);
    inorm_kernel<<<P_, RD_>>>(pE, pNF);

    // ---- mesh CSR build ----
    k_mdeg<<<B_*ME_/256, 256>>>(msrc, mdst);
    k_mscan<<<B_, M_>>>();
    mbucket_kernel<<<B_*ME_/256, 256>>>(msrc, mdst, mew);

    // ---- mesh layer 1 ----
    magg_k<RD_><<<dim3(B_*M_, RD_/128), 128>>>(pNF, pNFa);
    gemm_tf32<128,128,true><<<(B_*M_/128)*(HM_/128), 256, SM128>>>(
        pNFa, Wm1, pHM, B_*M_, HM_, RD_, pS1a, pS2a);
    k_mapply<true><<<dim3(HM_/128, B_*M_/64), 128>>>(
        pHM, pS1a, pS2a, gm1_g, gm1_b, gm1_a, pHMn, 0);

    // ---- mesh layer 2 ----
    magg_k<HM_><<<dim3(B_*M_, HM_/128), 128>>>(pHMn, pHMa);
    gemm_tf32<128,128,true><<<(B_*M_/128)*(HM_/128), 256, SM128>>>(
        pHMa, Wm2, pHM2, B_*M_, HM_, HM_, pS1b, pS2b);
    k_mapply<false><<<dim3(HM_/128, B_*M_/64), 128>>>(
        pHM2, pS1b, pS2b, gm2_g, gm2_b, gm2_a, nullptr, HM_);

    // ---- classifier ----
    final_kernel<<<1, 256>>>(Wc, out);
}